// round 2
// baseline (speedup 1.0000x reference)
#include <cuda_runtime.h>
#include <math.h>

#define NTOK 50176          // 16*56*56 = 128 windows * 392 tokens
#define CCH  128
#define LTOK 392
#define NWIN 128
#define NHEAD 4
#define HDIM 32
#define HIDDIM 512
#define TABLE 2535
#define QK_SCALE 0.17677669529663687f  // 32^-0.5

// ---- scratch (static device allocations; 16B-aligned for float4 paths) ----
__device__ __align__(16) float g_x  [NTOK * CCH];        // running activation, spatial layout
__device__ __align__(16) float g_xw [NTOK * CCH];        // LN'd + windowed
__device__ __align__(16) float g_qkv[NTOK * 3 * CCH];    // qkv, windowed
__device__ __align__(16) float g_att[NTOK * CCH];        // attention out, windowed
__device__ __align__(16) float g_y  [NTOK * CCH];        // LN2 out, spatial
__device__ __align__(16) float g_hid[NTOK * HIDDIM];     // MLP hidden

// ------------------------------------------------------------------
__global__ void copy_in_kernel(const float* __restrict__ src) {
    int i = blockIdx.x * 256 + threadIdx.x;
    g_x[i] = src[i];
}

// ------------------------------------------------------------------
// LayerNorm, one warp per token.
// mode 0: plain (spatial in -> spatial out)
// mode 1: windowed read (partition, no shift) -> windowed out
// mode 2: windowed read with shift (+4,+3,+3 roll) -> windowed out
__global__ __launch_bounds__(256) void ln_kernel(
    const float* __restrict__ x, const float* __restrict__ gw,
    const float* __restrict__ gb, float* __restrict__ out, int mode)
{
    int warp = threadIdx.x >> 5, lane = threadIdx.x & 31;
    int token = blockIdx.x * 8 + warp;
    int src;
    if (mode == 0) {
        src = token;
    } else {
        int wnd = token / LTOK, t = token - wnd * LTOK;
        int wd = wnd >> 6, wh = (wnd >> 3) & 7, ww = wnd & 7;
        int td = t / 49, r = t - td * 49, th = r / 7, tw = r - th * 7;
        int d = wd * 8 + td, h = wh * 7 + th, w = ww * 7 + tw;
        if (mode == 2) {
            d = (d + 4) & 15;
            h += 3; if (h >= 56) h -= 56;
            w += 3; if (w >= 56) w -= 56;
        }
        src = (d * 56 + h) * 56 + w;
    }
    const float* xp = x + (size_t)src * CCH;
    float v[4];
#pragma unroll
    for (int i = 0; i < 4; i++) v[i] = xp[lane + 32 * i];
    float s = v[0] + v[1] + v[2] + v[3];
#pragma unroll
    for (int o = 16; o; o >>= 1) s += __shfl_xor_sync(0xffffffffu, s, o);
    float mean = s * (1.f / 128.f);
    float q = 0.f;
#pragma unroll
    for (int i = 0; i < 4; i++) { float d0 = v[i] - mean; q += d0 * d0; }
#pragma unroll
    for (int o = 16; o; o >>= 1) q += __shfl_xor_sync(0xffffffffu, q, o);
    float inv = rsqrtf(q * (1.f / 128.f) + 1e-5f);
    float* op = out + (size_t)token * CCH;
#pragma unroll
    for (int i = 0; i < 4; i++) {
        int c = lane + 32 * i;
        op[c] = (v[i] - mean) * inv * gw[c] + gb[c];
    }
}

// ------------------------------------------------------------------
// Generic tiled fp32 GEMM: C = A[M,K] @ B[K,N] + bias, with epilogue modes.
// BM=BN=64, BK=16, 256 threads, 4x4 per thread.
// mode 0 (QKV):   scale cols < 128 by QK_SCALE, store row-major stride 384
// mode 1 (PROJ):  map windowed row -> spatial (with unshift), += into Cp
// mode 2 (FC1):   exact GELU, store stride 512
// mode 3 (FC2):   Cp[m] = resid[m] + v, stride 128
__global__ __launch_bounds__(256) void gemm_kernel(
    const float* __restrict__ A, const float* __restrict__ B,
    const float* __restrict__ bias, float* __restrict__ Cp,
    const float* __restrict__ resid, int K, int N, int mode, int shifted)
{
    __shared__ float As[16][64];
    __shared__ float Bs[16][64];
    int tid = threadIdx.x;
    int tx = tid & 15, ty = tid >> 4;
    int m0 = blockIdx.y * 64, n0 = blockIdx.x * 64;
    float acc[4][4] = {};
    int ar = tid >> 2, akq = tid & 3;   // A loader: row within tile, k-quad
    int bk = tid >> 4, bn = tid & 15;   // B loader

    for (int k0 = 0; k0 < K; k0 += 16) {
        float4 a4 = *(const float4*)(A + (size_t)(m0 + ar) * K + k0 + akq * 4);
        As[akq * 4 + 0][ar] = a4.x;
        As[akq * 4 + 1][ar] = a4.y;
        As[akq * 4 + 2][ar] = a4.z;
        As[akq * 4 + 3][ar] = a4.w;
        float4 b4 = *(const float4*)(B + (size_t)(k0 + bk) * N + n0 + bn * 4);
        *(float4*)&Bs[bk][bn * 4] = b4;
        __syncthreads();
#pragma unroll
        for (int kk = 0; kk < 16; kk++) {
            float4 a = *(const float4*)&As[kk][ty * 4];
            float4 b = *(const float4*)&Bs[kk][tx * 4];
            float av[4] = {a.x, a.y, a.z, a.w};
            float bv[4] = {b.x, b.y, b.z, b.w};
#pragma unroll
            for (int i = 0; i < 4; i++)
#pragma unroll
                for (int j = 0; j < 4; j++) acc[i][j] += av[i] * bv[j];
        }
        __syncthreads();
    }

    int gbase[4];
    if (mode == 1) {
#pragma unroll
        for (int i = 0; i < 4; i++) {
            int m = m0 + ty * 4 + i;
            int wnd = m / LTOK, t = m - wnd * LTOK;
            int wd = wnd >> 6, wh = (wnd >> 3) & 7, ww = wnd & 7;
            int td = t / 49, r = t - td * 49, th = r / 7, tw = r - th * 7;
            int d = wd * 8 + td, h = wh * 7 + th, w = ww * 7 + tw;
            if (shifted) {
                d = (d + 4) & 15;
                h += 3; if (h >= 56) h -= 56;
                w += 3; if (w >= 56) w -= 56;
            }
            gbase[i] = ((d * 56 + h) * 56 + w) * CCH;
        }
    }

#pragma unroll
    for (int i = 0; i < 4; i++) {
        int m = m0 + ty * 4 + i;
#pragma unroll
        for (int j = 0; j < 4; j++) {
            int n = n0 + tx * 4 + j;
            float v = acc[i][j] + bias[n];
            if (mode == 0) {
                if (n < CCH) v *= QK_SCALE;
                Cp[(size_t)m * 384 + n] = v;
            } else if (mode == 1) {
                Cp[(size_t)gbase[i] + n] += v;
            } else if (mode == 2) {
                v = 0.5f * v * (1.f + erff(v * 0.70710678118654752f));
                Cp[(size_t)m * HIDDIM + n] = v;
            } else {
                Cp[(size_t)m * CCH + n] = resid[(size_t)m * CCH + n] + v;
            }
        }
    }
}

// ------------------------------------------------------------------
// Attention: one CTA per (window, head). K,V in padded smem (stride 33),
// one warp per query row, 13 keys per lane, online softmax, p-row in smem.
#define KROWS 416   // 392 rounded up to 13*32; rows >=392 zero-padded
__global__ __launch_bounds__(256) void attn_kernel(
    const float* __restrict__ qkv, const float* __restrict__ rpb,
    float* __restrict__ out, int use_mask)
{
    extern __shared__ float sm[];
    float* Ksh = sm;                       // KROWS*33
    float* Vsh = Ksh + KROWS * 33;         // KROWS*33
    float* P   = Vsh + KROWS * 33;         // 8*392
    int*   enc = (int*)(P + 8 * LTOK);     // 392 packed (label<<12)|(td<<8)|(th<<4)|tw

    int wnd = blockIdx.x, head = blockIdx.y;
    int tid = threadIdx.x;
    const float* base = qkv + (size_t)wnd * LTOK * 384 + head * HDIM;

    for (int idx = tid; idx < KROWS * 32; idx += 256) {
        int m = idx >> 5, d2 = idx & 31;
        float kv = 0.f, vv = 0.f;
        if (m < LTOK) {
            kv = base[(size_t)m * 384 + 128 + d2];
            vv = base[(size_t)m * 384 + 256 + d2];
        }
        Ksh[m * 33 + d2] = kv;
        Vsh[m * 33 + d2] = vv;
    }
    {
        int wd = wnd >> 6, wh = (wnd >> 3) & 7, ww = wnd & 7;
        for (int t = tid; t < LTOK; t += 256) {
            int td = t / 49, r = t - td * 49, th = r / 7, tw = r - th * 7;
            int d = wd * 8 + td, h = wh * 7 + th, w = ww * 7 + tw;
            int rd = d < 8 ? 0 : (d < 12 ? 1 : 2);
            int rh = h < 49 ? 0 : (h < 53 ? 1 : 2);
            int rw = w < 49 ? 0 : (w < 53 ? 1 : 2);
            int label = rd * 9 + rh * 3 + rw;
            enc[t] = (label << 12) | (td << 8) | (th << 4) | tw;
        }
    }
    __syncthreads();

    int warp = tid >> 5, lane = tid & 31;
    float* pw = P + warp * LTOK;

    for (int row = warp; row < LTOK; row += 8) {
        int re = enc[row];
        int rtd = (re >> 8) & 15, rth = (re >> 4) & 15, rtw = re & 15, rlab = re >> 12;
        float qv = base[(size_t)row * 384 + lane];

        float s[13];
#pragma unroll
        for (int i = 0; i < 13; i++) {
            int m = lane + 32 * i;
            if (m < LTOK) {
                int me = enc[m];
                int idx = (rtd - ((me >> 8) & 15) + 7) * 169
                        + (rth - ((me >> 4) & 15) + 6) * 13
                        + (rtw - (me & 15) + 6);
                float v = rpb[idx * NHEAD + head];
                if (use_mask && (me >> 12) != rlab) v -= 100.f;
                s[i] = v;
            } else {
                s[i] = -1e30f;
            }
        }
#pragma unroll
        for (int d2 = 0; d2 < 32; d2++) {
            float qd = __shfl_sync(0xffffffffu, qv, d2);
#pragma unroll
            for (int i = 0; i < 13; i++)
                s[i] += qd * Ksh[(lane + 32 * i) * 33 + d2];
        }
        float mx = s[0];
#pragma unroll
        for (int i = 1; i < 13; i++) mx = fmaxf(mx, s[i]);
#pragma unroll
        for (int o = 16; o; o >>= 1) mx = fmaxf(mx, __shfl_xor_sync(0xffffffffu, mx, o));
        float sum = 0.f;
        float e[13];
#pragma unroll
        for (int i = 0; i < 13; i++) { e[i] = __expf(s[i] - mx); sum += e[i]; }
#pragma unroll
        for (int o = 16; o; o >>= 1) sum += __shfl_xor_sync(0xffffffffu, sum, o);
        float inv = 1.f / sum;
#pragma unroll
        for (int i = 0; i < 13; i++) {
            int m = lane + 32 * i;
            if (m < LTOK) pw[m] = e[i] * inv;
        }
        __syncwarp();
        float acc = 0.f;
#pragma unroll 4
        for (int m = 0; m < LTOK; m++) acc += pw[m] * Vsh[m * 33 + lane];
        out[((size_t)wnd * LTOK + row) * CCH + head * HDIM + lane] = acc;
        __syncwarp();
    }
}

// ------------------------------------------------------------------
extern "C" void kernel_launch(void* const* d_in, const int* in_sizes, int n_in,
                              void* d_out, int out_size)
{
    const float* x_in   = (const float*)d_in[0];
    const float* ln1_g  = (const float*)d_in[1];
    const float* ln1_b  = (const float*)d_in[2];
    const float* qkv_w  = (const float*)d_in[3];
    const float* qkv_b  = (const float*)d_in[4];
    const float* rpb    = (const float*)d_in[5];
    const float* proj_w = (const float*)d_in[6];
    const float* proj_b = (const float*)d_in[7];
    const float* ln2_g  = (const float*)d_in[8];
    const float* ln2_b  = (const float*)d_in[9];
    const float* fc1_w  = (const float*)d_in[10];
    const float* fc1_b  = (const float*)d_in[11];
    const float* fc2_w  = (const float*)d_in[12];
    const float* fc2_b  = (const float*)d_in[13];

    float *px, *pxw, *pqkv, *patt, *py, *phid;
    cudaGetSymbolAddress((void**)&px,   g_x);
    cudaGetSymbolAddress((void**)&pxw,  g_xw);
    cudaGetSymbolAddress((void**)&pqkv, g_qkv);
    cudaGetSymbolAddress((void**)&patt, g_att);
    cudaGetSymbolAddress((void**)&py,   g_y);
    cudaGetSymbolAddress((void**)&phid, g_hid);

    const int ATTN_SMEM = (KROWS * 33 * 2 + 8 * LTOK) * 4 + LTOK * 4;
    cudaFuncSetAttribute(attn_kernel, cudaFuncAttributeMaxDynamicSharedMemorySize, ATTN_SMEM);

    copy_in_kernel<<<NTOK * CCH / 256, 256>>>(x_in);

    for (int i = 0; i < 2; i++) {
        // LN1 + (shift) + window partition
        ln_kernel<<<NTOK / 8, 256>>>(px, ln1_g + i * 128, ln1_b + i * 128, pxw, i ? 2 : 1);
        // QKV GEMM (q scaled)
        gemm_kernel<<<dim3(6, 784), 256>>>(pxw, qkv_w + i * 128 * 384, qkv_b + i * 384,
                                           pqkv, nullptr, 128, 384, 0, 0);
        // windowed attention (+rel bias, +mask for block 1)
        attn_kernel<<<dim3(NWIN, NHEAD), 256, ATTN_SMEM>>>(pqkv, rpb + i * TABLE * NHEAD, patt, i);
        // proj GEMM + window reverse + unshift + residual add into g_x
        gemm_kernel<<<dim3(2, 784), 256>>>(patt, proj_w + i * 128 * 128, proj_b + i * 128,
                                           px, nullptr, 128, 128, 1, i);
        // LN2 (spatial)
        ln_kernel<<<NTOK / 8, 256>>>(px, ln2_g + i * 128, ln2_b + i * 128, py, 0);
        // FC1 + GELU
        gemm_kernel<<<dim3(8, 784), 256>>>(py, fc1_w + i * 128 * 512, fc1_b + i * 512,
                                           phid, nullptr, 128, 512, 2, 0);
        // FC2 + residual; block 1 writes final output
        float* outp = (i == 1) ? (float*)d_out : px;
        gemm_kernel<<<dim3(2, 784), 256>>>(phid, fc2_w + i * 512 * 128, fc2_b + i * 128,
                                           outp, px, 512, 128, 3, 0);
    }
}

// round 3
// speedup vs baseline: 1.5908x; 1.5908x over previous
#include <cuda_runtime.h>
#include <math.h>

#define NTOK 50176          // 16*56*56 = 128 windows * 392 tokens
#define CCH  128
#define LTOK 392
#define NWIN 128
#define NHEAD 4
#define HDIM 32
#define HIDDIM 512
#define TABLE 2535
#define QK_SCALE 0.17677669529663687f  // 32^-0.5

// ---- scratch (static device allocations; 16B-aligned) ----
__device__ __align__(16) float g_x  [NTOK * CCH];
__device__ __align__(16) float g_xw [NTOK * CCH];
__device__ __align__(16) float g_qkv[NTOK * 3 * CCH];
__device__ __align__(16) float g_att[NTOK * CCH];
__device__ __align__(16) float g_y  [NTOK * CCH];
__device__ __align__(16) float g_hid[NTOK * HIDDIM];

// ------------------------------------------------------------------
__global__ void copy_in_kernel(const float* __restrict__ src) {
    int i = blockIdx.x * 256 + threadIdx.x;
    g_x[i] = src[i];
}

// ------------------------------------------------------------------
// LayerNorm, one warp per token. mode 0 plain, 1 windowed, 2 windowed+shift.
__global__ __launch_bounds__(256) void ln_kernel(
    const float* __restrict__ x, const float* __restrict__ gw,
    const float* __restrict__ gb, float* __restrict__ out, int mode)
{
    int warp = threadIdx.x >> 5, lane = threadIdx.x & 31;
    int token = blockIdx.x * 8 + warp;
    int src;
    if (mode == 0) {
        src = token;
    } else {
        int wnd = token / LTOK, t = token - wnd * LTOK;
        int wd = wnd >> 6, wh = (wnd >> 3) & 7, ww = wnd & 7;
        int td = t / 49, r = t - td * 49, th = r / 7, tw = r - th * 7;
        int d = wd * 8 + td, h = wh * 7 + th, w = ww * 7 + tw;
        if (mode == 2) {
            d = (d + 4) & 15;
            h += 3; if (h >= 56) h -= 56;
            w += 3; if (w >= 56) w -= 56;
        }
        src = (d * 56 + h) * 56 + w;
    }
    const float* xp = x + (size_t)src * CCH;
    float v[4];
#pragma unroll
    for (int i = 0; i < 4; i++) v[i] = xp[lane + 32 * i];
    float s = v[0] + v[1] + v[2] + v[3];
#pragma unroll
    for (int o = 16; o; o >>= 1) s += __shfl_xor_sync(0xffffffffu, s, o);
    float mean = s * (1.f / 128.f);
    float q = 0.f;
#pragma unroll
    for (int i = 0; i < 4; i++) { float d0 = v[i] - mean; q += d0 * d0; }
#pragma unroll
    for (int o = 16; o; o >>= 1) q += __shfl_xor_sync(0xffffffffu, q, o);
    float inv = rsqrtf(q * (1.f / 128.f) + 1e-5f);
    float* op = out + (size_t)token * CCH;
#pragma unroll
    for (int i = 0; i < 4; i++) {
        int c = lane + 32 * i;
        op[c] = (v[i] - mean) * inv * gw[c] + gb[c];
    }
}

// ------------------------------------------------------------------
// GEMM: C = A[M,K] @ B[K,N] + bias. BM=BN=128, BK=16, 256 thr, 8x8/thread.
// Inner loop uses packed fma.rn.f32x2 (FFMA2). A stored duplicated in smem
// so a-operand pairs come straight from ld.shared.b64.
// dynamic smem: 49152 B = A2 two stages (16*256 fl each) + B two stages (16*128 fl each)
// mode 0 QKV (scale q cols, stride 384) | 1 proj scatter+residual | 2 GELU s512 | 3 resid s128
__global__ __launch_bounds__(256, 2) void gemm_kernel(
    const float* __restrict__ A, const float* __restrict__ B,
    const float* __restrict__ bias, float* __restrict__ Cp,
    const float* __restrict__ resid, int K, int N, int mode, int shifted)
{
    extern __shared__ float gsm[];   // [0,8192): As2 stages, [8192,12288): Bs stages
    int tid = threadIdx.x;
    int txn = (tid & 15) * 8;        // n offset in tile
    int tym = (tid >> 4) * 8;        // m offset in tile
    int m0 = blockIdx.y * 128, n0 = blockIdx.x * 128;

    int arow = tid >> 1;             // 0..127
    int kh   = (tid & 1) * 8;        // 0 or 8
    int bk   = tid >> 4;             // 0..15
    int bn   = (tid & 15) * 8;

    const float* Ap = A + (size_t)(m0 + arow) * K + kh;
    const float* Bp = B + (size_t)bk * N + n0 + bn;

    unsigned long long acc[8][4];
#pragma unroll
    for (int i = 0; i < 8; i++)
#pragma unroll
        for (int j = 0; j < 4; j++) acc[i][j] = 0ull;

    float4 ra0, ra1, rb0, rb1;
    ra0 = *(const float4*)(Ap);
    ra1 = *(const float4*)(Ap + 4);
    rb0 = *(const float4*)(Bp);
    rb1 = *(const float4*)(Bp + 4);

#define STORE_STAGE(p) do {                                              \
        float* asb = gsm + (p) * 4096 + kh * 256 + arow * 2;             \
        *(float2*)(asb +    0) = make_float2(ra0.x, ra0.x);              \
        *(float2*)(asb +  256) = make_float2(ra0.y, ra0.y);              \
        *(float2*)(asb +  512) = make_float2(ra0.z, ra0.z);              \
        *(float2*)(asb +  768) = make_float2(ra0.w, ra0.w);              \
        *(float2*)(asb + 1024) = make_float2(ra1.x, ra1.x);              \
        *(float2*)(asb + 1280) = make_float2(ra1.y, ra1.y);              \
        *(float2*)(asb + 1536) = make_float2(ra1.z, ra1.z);              \
        *(float2*)(asb + 1792) = make_float2(ra1.w, ra1.w);              \
        float* bsb = gsm + 8192 + (p) * 2048 + bk * 128 + bn;            \
        *(float4*)(bsb) = rb0; *(float4*)(bsb + 4) = rb1;                \
    } while (0)

    STORE_STAGE(0);
    __syncthreads();

    int KT = K >> 4;
    for (int kt = 1; kt <= KT; kt++) {
        int p = (kt - 1) & 1;
        if (kt < KT) {
            ra0 = *(const float4*)(Ap + kt * 16);
            ra1 = *(const float4*)(Ap + kt * 16 + 4);
            rb0 = *(const float4*)(Bp + (size_t)kt * 16 * N);
            rb1 = *(const float4*)(Bp + (size_t)kt * 16 * N + 4);
        }
        unsigned sa = (unsigned)__cvta_generic_to_shared(gsm + p * 4096 + tym * 2);
        unsigned sb = (unsigned)__cvta_generic_to_shared(gsm + 8192 + p * 2048 + txn);
#pragma unroll
        for (int kk = 0; kk < 16; kk++) {
            unsigned long long a2[8], b2[4];
            asm volatile("ld.shared.v2.b64 {%0,%1},[%2];"
                         : "=l"(b2[0]), "=l"(b2[1]) : "r"(sb + kk * 512));
            asm volatile("ld.shared.v2.b64 {%0,%1},[%2];"
                         : "=l"(b2[2]), "=l"(b2[3]) : "r"(sb + kk * 512 + 16));
#pragma unroll
            for (int i = 0; i < 8; i++)
                asm volatile("ld.shared.b64 %0,[%1];"
                             : "=l"(a2[i]) : "r"(sa + kk * 1024 + i * 8));
#pragma unroll
            for (int i = 0; i < 8; i++)
#pragma unroll
                for (int j = 0; j < 4; j++)
                    asm("fma.rn.f32x2 %0,%1,%2,%0;"
                        : "+l"(acc[i][j]) : "l"(a2[i]), "l"(b2[j]));
        }
        if (kt < KT) STORE_STAGE(kt & 1);
        __syncthreads();
    }

    // epilogue
    float bs[8];
    {
        float4 b4a = *(const float4*)(bias + n0 + txn);
        float4 b4b = *(const float4*)(bias + n0 + txn + 4);
        bs[0]=b4a.x; bs[1]=b4a.y; bs[2]=b4a.z; bs[3]=b4a.w;
        bs[4]=b4b.x; bs[5]=b4b.y; bs[6]=b4b.z; bs[7]=b4b.w;
    }
#pragma unroll
    for (int i = 0; i < 8; i++) {
        int m = m0 + tym + i;
        float vo[8];
#pragma unroll
        for (int j = 0; j < 4; j++) {
            float2 t = *(float2*)&acc[i][j];
            vo[j*2] = t.x + bs[j*2];
            vo[j*2+1] = t.y + bs[j*2+1];
        }
        if (mode == 0) {
            float sc = (n0 == 0) ? QK_SCALE : 1.f;
            float4 o0 = make_float4(vo[0]*sc, vo[1]*sc, vo[2]*sc, vo[3]*sc);
            float4 o1 = make_float4(vo[4]*sc, vo[5]*sc, vo[6]*sc, vo[7]*sc);
            float* dst = Cp + (size_t)m * 384 + n0 + txn;
            *(float4*)dst = o0; *(float4*)(dst + 4) = o1;
        } else if (mode == 1) {
            int wnd = m / LTOK, t = m - wnd * LTOK;
            int wd = wnd >> 6, wh = (wnd >> 3) & 7, ww = wnd & 7;
            int td = t / 49, r = t - td * 49, th = r / 7, tw = r - th * 7;
            int d = wd * 8 + td, h = wh * 7 + th, w = ww * 7 + tw;
            if (shifted) {
                d = (d + 4) & 15;
                h += 3; if (h >= 56) h -= 56;
                w += 3; if (w >= 56) w -= 56;
            }
            float* dst = Cp + (size_t)((d * 56 + h) * 56 + w) * CCH + n0 + txn;
            float4 o0 = *(float4*)dst, o1 = *(float4*)(dst + 4);
            o0.x += vo[0]; o0.y += vo[1]; o0.z += vo[2]; o0.w += vo[3];
            o1.x += vo[4]; o1.y += vo[5]; o1.z += vo[6]; o1.w += vo[7];
            *(float4*)dst = o0; *(float4*)(dst + 4) = o1;
        } else if (mode == 2) {
#pragma unroll
            for (int j = 0; j < 8; j++)
                vo[j] = 0.5f * vo[j] * (1.f + erff(vo[j] * 0.70710678118654752f));
            float* dst = Cp + (size_t)m * HIDDIM + n0 + txn;
            *(float4*)dst = make_float4(vo[0], vo[1], vo[2], vo[3]);
            *(float4*)(dst + 4) = make_float4(vo[4], vo[5], vo[6], vo[7]);
        } else {
            const float* rp = resid + (size_t)m * CCH + n0 + txn;
            float4 r0 = *(const float4*)rp, r1 = *(const float4*)(rp + 4);
            float* dst = Cp + (size_t)m * CCH + n0 + txn;
            *(float4*)dst = make_float4(r0.x + vo[0], r0.y + vo[1], r0.z + vo[2], r0.w + vo[3]);
            *(float4*)(dst + 4) = make_float4(r1.x + vo[4], r1.y + vo[5], r1.z + vo[6], r1.w + vo[7]);
        }
    }
#undef STORE_STAGE
}

// ------------------------------------------------------------------
// Attention: CTA = (window, head), 8 warps, warp handles 49 rows in 7 chunks of 7.
// S tile (7 rows x 13 keys/lane) in registers; K once/chunk; V (transposed) once/chunk;
// P staged per-warp in smem; PV uses packed f32x2 FMAs; rpb head-slice staged in smem.
// smem layout (floats): Ksh[392*33] | Vt[32*420] | Ps[8*2800] | rpbs[2535] | enc[392 ints]
#define ATT_SMEM_FLOATS (12936 + 13440 + 22400 + 2535 + 392)
__global__ __launch_bounds__(256, 1) void attn_kernel(
    const float* __restrict__ qkv, const float* __restrict__ rpb,
    float* __restrict__ out, int use_mask)
{
    extern __shared__ float sm[];
    float* Ksh  = sm;
    float* Vt   = sm + 12936;
    float* Ps   = sm + 12936 + 13440;
    float* rpbs = sm + 12936 + 13440 + 22400;
    int*   enc  = (int*)(rpbs + TABLE);

    int wnd = blockIdx.x, head = blockIdx.y;
    int tid = threadIdx.x;
    const float* base = qkv + (size_t)wnd * LTOK * 384 + head * HDIM;

    for (int idx = tid; idx < LTOK * 32; idx += 256) {
        int m = idx >> 5, d = idx & 31;
        float kv = base[(size_t)m * 384 + 128 + d];
        float vv = base[(size_t)m * 384 + 256 + d];
        Ksh[m * 33 + d] = kv;
        Vt[d * 420 + m] = vv;
    }
    for (int i = tid; i < TABLE; i += 256) rpbs[i] = rpb[i * NHEAD + head];
    {
        int wd = wnd >> 6, wh = (wnd >> 3) & 7, ww = wnd & 7;
        for (int t = tid; t < LTOK; t += 256) {
            int td = t / 49, r = t - td * 49, th = r / 7, tw = r - th * 7;
            int d = wd * 8 + td, h = wh * 7 + th, w = ww * 7 + tw;
            int rd = d < 8 ? 0 : (d < 12 ? 1 : 2);
            int rh = h < 49 ? 0 : (h < 53 ? 1 : 2);
            int rw = w < 49 ? 0 : (w < 53 ? 1 : 2);
            enc[t] = ((rd * 9 + rh * 3 + rw) << 12) | (td << 8) | (th << 4) | tw;
        }
    }
    __syncthreads();

    int warp = tid >> 5, lane = tid & 31;
    float* Pw = Ps + warp * 2800;
    unsigned pw_base = (unsigned)__cvta_generic_to_shared(Pw);
    unsigned vt_base = (unsigned)__cvta_generic_to_shared(Vt + lane * 420);

    int moff[13], mval[13], menc[13];
#pragma unroll
    for (int i = 0; i < 13; i++) {
        int m = lane + 32 * i;
        mval[i] = (m < LTOK);
        moff[i] = (mval[i] ? m : LTOK - 1) * 33;
        menc[i] = enc[mval[i] ? m : 0];
    }

    int rbase0 = warp * 49;
    for (int c = 0; c < 7; c++) {
        int r0 = rbase0 + c * 7;
        float qreg[7];
        int rtd[7], rth[7], rtw[7], rl[7];
#pragma unroll
        for (int j = 0; j < 7; j++) {
            qreg[j] = base[(size_t)(r0 + j) * 384 + lane];
            int re = enc[r0 + j];
            rtd[j] = (re >> 8) & 15; rth[j] = (re >> 4) & 15;
            rtw[j] = re & 15; rl[j] = re >> 12;
        }
        float s[7][13];
#pragma unroll
        for (int i = 0; i < 13; i++) {
            int me = menc[i];
            int mtd = (me >> 8) & 15, mth = (me >> 4) & 15, mtw = me & 15, ml = me >> 12;
#pragma unroll
            for (int j = 0; j < 7; j++) {
                float b = rpbs[(rtd[j] - mtd + 7) * 169 + (rth[j] - mth + 6) * 13
                               + (rtw[j] - mtw + 6)];
                if (use_mask && ml != rl[j]) b -= 100.f;
                s[j][i] = mval[i] ? b : -1e30f;
            }
        }
        // QK^T
#pragma unroll 4
        for (int d2 = 0; d2 < 32; d2++) {
            float kv[13];
#pragma unroll
            for (int i = 0; i < 13; i++) kv[i] = Ksh[moff[i] + d2];
#pragma unroll
            for (int j = 0; j < 7; j++) {
                float qb = __shfl_sync(0xffffffffu, qreg[j], d2);
#pragma unroll
                for (int i = 0; i < 13; i++) s[j][i] += qb * kv[i];
            }
        }
        // softmax + P store
#pragma unroll
        for (int j = 0; j < 7; j++) {
            float mx = s[j][0];
#pragma unroll
            for (int i = 1; i < 13; i++) mx = fmaxf(mx, s[j][i]);
#pragma unroll
            for (int o = 16; o; o >>= 1) mx = fmaxf(mx, __shfl_xor_sync(0xffffffffu, mx, o));
            float sum = 0.f;
#pragma unroll
            for (int i = 0; i < 13; i++) { float e = __expf(s[j][i] - mx); s[j][i] = e; sum += e; }
#pragma unroll
            for (int o = 16; o; o >>= 1) sum += __shfl_xor_sync(0xffffffffu, sum, o);
            float inv = 1.f / sum;
#pragma unroll
            for (int i = 0; i < 13; i++)
                if (mval[i]) Pw[j * 400 + lane + 32 * i] = s[j][i] * inv;
        }
        __syncwarp();
        // P @ V with packed f32x2
        unsigned long long acc2[7];
#pragma unroll
        for (int j = 0; j < 7; j++) acc2[j] = 0ull;
        for (int m4 = 0; m4 < LTOK; m4 += 4) {
            unsigned long long va, vb;
            asm volatile("ld.shared.v2.b64 {%0,%1},[%2];"
                         : "=l"(va), "=l"(vb) : "r"(vt_base + m4 * 4));
#pragma unroll
            for (int j = 0; j < 7; j++) {
                unsigned long long pa, pb;
                asm volatile("ld.shared.v2.b64 {%0,%1},[%2];"
                             : "=l"(pa), "=l"(pb) : "r"(pw_base + (j * 400 + m4) * 4));
                asm("fma.rn.f32x2 %0,%1,%2,%0;" : "+l"(acc2[j]) : "l"(pa), "l"(va));
                asm("fma.rn.f32x2 %0,%1,%2,%0;" : "+l"(acc2[j]) : "l"(pb), "l"(vb));
            }
        }
#pragma unroll
        for (int j = 0; j < 7; j++) {
            float2 f = *(float2*)&acc2[j];
            out[((size_t)wnd * LTOK + r0 + j) * CCH + head * HDIM + lane] = f.x + f.y;
        }
        __syncwarp();
    }
}

// ------------------------------------------------------------------
extern "C" void kernel_launch(void* const* d_in, const int* in_sizes, int n_in,
                              void* d_out, int out_size)
{
    const float* x_in   = (const float*)d_in[0];
    const float* ln1_g  = (const float*)d_in[1];
    const float* ln1_b  = (const float*)d_in[2];
    const float* qkv_w  = (const float*)d_in[3];
    const float* qkv_b  = (const float*)d_in[4];
    const float* rpb    = (const float*)d_in[5];
    const float* proj_w = (const float*)d_in[6];
    const float* proj_b = (const float*)d_in[7];
    const float* ln2_g  = (const float*)d_in[8];
    const float* ln2_b  = (const float*)d_in[9];
    const float* fc1_w  = (const float*)d_in[10];
    const float* fc1_b  = (const float*)d_in[11];
    const float* fc2_w  = (const float*)d_in[12];
    const float* fc2_b  = (const float*)d_in[13];

    float *px, *pxw, *pqkv, *patt, *py, *phid;
    cudaGetSymbolAddress((void**)&px,   g_x);
    cudaGetSymbolAddress((void**)&pxw,  g_xw);
    cudaGetSymbolAddress((void**)&pqkv, g_qkv);
    cudaGetSymbolAddress((void**)&patt, g_att);
    cudaGetSymbolAddress((void**)&py,   g_y);
    cudaGetSymbolAddress((void**)&phid, g_hid);

    const int ATTN_SMEM = ATT_SMEM_FLOATS * 4;         // 206812 B
    const int GEMM_SMEM = 49152;
    cudaFuncSetAttribute(attn_kernel, cudaFuncAttributeMaxDynamicSharedMemorySize, ATTN_SMEM);
    cudaFuncSetAttribute(gemm_kernel, cudaFuncAttributeMaxDynamicSharedMemorySize, GEMM_SMEM);

    copy_in_kernel<<<NTOK * CCH / 256, 256>>>(x_in);

    for (int i = 0; i < 2; i++) {
        ln_kernel<<<NTOK / 8, 256>>>(px, ln1_g + i * 128, ln1_b + i * 128, pxw, i ? 2 : 1);
        gemm_kernel<<<dim3(3, 392), 256, GEMM_SMEM>>>(pxw, qkv_w + i * 128 * 384,
                                                      qkv_b + i * 384, pqkv, nullptr,
                                                      128, 384, 0, 0);
        attn_kernel<<<dim3(NWIN, NHEAD), 256, ATTN_SMEM>>>(pqkv, rpb + i * TABLE * NHEAD,
                                                           patt, i);
        gemm_kernel<<<dim3(1, 392), 256, GEMM_SMEM>>>(patt, proj_w + i * 128 * 128,
                                                      proj_b + i * 128, px, nullptr,
                                                      128, 128, 1, i);
        ln_kernel<<<NTOK / 8, 256>>>(px, ln2_g + i * 128, ln2_b + i * 128, py, 0);
        gemm_kernel<<<dim3(4, 392), 256, GEMM_SMEM>>>(py, fc1_w + i * 128 * 512,
                                                      fc1_b + i * 512, phid, nullptr,
                                                      128, 512, 2, 0);
        float* outp = (i == 1) ? (float*)d_out : px;
        gemm_kernel<<<dim3(1, 392), 256, GEMM_SMEM>>>(phid, fc2_w + i * 512 * 128,
                                                      fc2_b + i * 128, outp, px,
                                                      512, 128, 3, 0);
    }
}

// round 6
// speedup vs baseline: 2.4381x; 1.5326x over previous
#include <cuda_runtime.h>
#include <math.h>
#include <stdint.h>

#define NTOK 50176          // 16*56*56 = 392*128
#define CCH  128
#define LTOK 392
#define NWIN 128
#define NHEAD 4
#define HDIM 32
#define HIDDIM 512
#define TABLE 2535
#define QK_SCALE 0.17677669529663687f

// ---- scratch ----
__device__ __align__(16) float g_x  [NTOK * CCH];
__device__ __align__(16) float g_xw [NTOK * CCH];
__device__ __align__(16) float g_qkv[NTOK * 3 * CCH];
__device__ __align__(16) float g_att[NTOK * CCH];
__device__ __align__(16) float g_y  [NTOK * CCH];
__device__ __align__(16) float g_hid[NTOK * HIDDIM];
__device__ __align__(16) float g_bt [393216];          // transposed weights, 2 blocks

// ------------------------------------------------------------------
__global__ void copy_in_kernel(const float* __restrict__ src) {
    int i = blockIdx.x * 256 + threadIdx.x;
    g_x[i] = src[i];
}

// out[n*K+k] = in[k*N+n]
__global__ void transpose_kernel(const float* __restrict__ in, float* __restrict__ out,
                                 int K, int N) {
    __shared__ float t[32][33];
    int kb = blockIdx.x * 32, nb = blockIdx.y * 32;
    int tx = threadIdx.x, ty = threadIdx.y;           // 32 x 8
    for (int r = ty; r < 32; r += 8) {
        int k = kb + r, n = nb + tx;
        t[r][tx] = (k < K && n < N) ? in[(size_t)k * N + n] : 0.f;
    }
    __syncthreads();
    for (int r = ty; r < 32; r += 8) {
        int n = nb + r, k = kb + tx;
        if (n < N && k < K) out[(size_t)n * K + k] = t[tx][r];
    }
}

// ------------------------------------------------------------------
// LayerNorm, one warp per token. mode 0 plain, 1 windowed, 2 windowed+shift.
__global__ __launch_bounds__(256) void ln_kernel(
    const float* __restrict__ x, const float* __restrict__ gw,
    const float* __restrict__ gb, float* __restrict__ out, int mode)
{
    int warp = threadIdx.x >> 5, lane = threadIdx.x & 31;
    int token = blockIdx.x * 8 + warp;
    int src;
    if (mode == 0) {
        src = token;
    } else {
        int wnd = token / LTOK, t = token - wnd * LTOK;
        int wd = wnd >> 6, wh = (wnd >> 3) & 7, ww = wnd & 7;
        int td = t / 49, r = t - td * 49, th = r / 7, tw = r - th * 7;
        int d = wd * 8 + td, h = wh * 7 + th, w = ww * 7 + tw;
        if (mode == 2) {
            d = (d + 4) & 15;
            h += 3; if (h >= 56) h -= 56;
            w += 3; if (w >= 56) w -= 56;
        }
        src = (d * 56 + h) * 56 + w;
    }
    const float* xp = x + (size_t)src * CCH;
    float v[4];
#pragma unroll
    for (int i = 0; i < 4; i++) v[i] = xp[lane + 32 * i];
    float s = v[0] + v[1] + v[2] + v[3];
#pragma unroll
    for (int o = 16; o; o >>= 1) s += __shfl_xor_sync(0xffffffffu, s, o);
    float mean = s * (1.f / 128.f);
    float q = 0.f;
#pragma unroll
    for (int i = 0; i < 4; i++) { float d0 = v[i] - mean; q += d0 * d0; }
#pragma unroll
    for (int o = 16; o; o >>= 1) q += __shfl_xor_sync(0xffffffffu, q, o);
    float inv = rsqrtf(q * (1.f / 128.f) + 1e-5f);
    float* op = out + (size_t)token * CCH;
#pragma unroll
    for (int i = 0; i < 4; i++) {
        int c = lane + 32 * i;
        op[c] = (v[i] - mean) * inv * gw[c] + gb[c];
    }
}

// ------------------------------------------------------------------
__device__ __forceinline__ unsigned s2u(const void* p) {
    unsigned a;
    asm("{ .reg .u64 t; cvta.to.shared.u64 t, %1; cvt.u32.u64 %0, t; }" : "=r"(a) : "l"(p));
    return a;
}
__device__ __forceinline__ void cp16(unsigned dst, const void* src) {
    asm volatile("cp.async.ca.shared.global [%0], [%1], 16;" :: "r"(dst), "l"(src));
}
__device__ __forceinline__ void mma_tf32(float c[4], const uint32_t a[4], const uint32_t b[2]) {
    asm volatile(
        "mma.sync.aligned.m16n8k8.row.col.f32.tf32.tf32.f32 "
        "{%0,%1,%2,%3}, {%4,%5,%6,%7}, {%8,%9}, {%0,%1,%2,%3};"
        : "+f"(c[0]), "+f"(c[1]), "+f"(c[2]), "+f"(c[3])
        : "r"(a[0]), "r"(a[1]), "r"(a[2]), "r"(a[3]), "r"(b[0]), "r"(b[1]));
}

// ------------------------------------------------------------------
// mma.sync tf32 GEMM: C[M,N] = A[M,K] @ Bt[N,K]^T + bias. 128x128/CTA, 8 warps,
// warp tile 32x64 (2x8 m16n8k8). BK=32, cp.async double buffer, stride-36 smem.
// mode 0 QKV (scale n0==0 tile, stride 384) | 1 proj scatter+residual
// mode 2 GELU stride 512 | 3 residual stride 128
#define GEMM_SMEM (18432 * 4)     // 2 stages * (A 4608 + B 4608) floats
__global__ __launch_bounds__(256, 2) void gemm_mma_kernel(
    const float* __restrict__ A, const float* __restrict__ Bt,
    const float* __restrict__ bias, float* __restrict__ Cp,
    const float* __restrict__ resid, int K, int N, int mode, int shifted)
{
    extern __shared__ float gsm[];
    int tid = threadIdx.x, wid = tid >> 5, lane = tid & 31;
    int warp_m = wid & 3, warp_n = wid >> 2;
    int m0 = blockIdx.y * 128, n0 = blockIdx.x * 128;
    unsigned smu = s2u(gsm);

    const float* Abase = A + (size_t)m0 * K;
    const float* Bbase = Bt + (size_t)n0 * K;

    // cp.async loader: 1024 16B-chunks per tile per chunk; 4 per thread each for A,B
    int lrow = tid >> 1;                  // 0..127 (2 threads/row)
    int lk4h = (tid & 1) * 4;             // chunk-halves: k4 in [0..3] or [4..7]

#define ISSUE_CHUNK(kc, st) do {                                               \
        const float* as = Abase + (size_t)lrow * K + (kc) * 32 + lk4h * 4;     \
        const float* bs = Bbase + (size_t)lrow * K + (kc) * 32 + lk4h * 4;     \
        unsigned ad = smu + ((st) * 9216 + lrow * 36 + lk4h * 4) * 4;          \
        unsigned bd = smu + ((st) * 9216 + 4608 + lrow * 36 + lk4h * 4) * 4;   \
        cp16(ad,      as);      cp16(bd,      bs);                             \
        cp16(ad + 16, as + 4);  cp16(bd + 16, bs + 4);                         \
        cp16(ad + 32, as + 8);  cp16(bd + 32, bs + 8);                         \
        cp16(ad + 48, as + 12); cp16(bd + 48, bs + 12);                        \
        asm volatile("cp.async.commit_group;");                                \
    } while (0)

    float acc[2][8][4];
#pragma unroll
    for (int mt = 0; mt < 2; mt++)
#pragma unroll
        for (int nt = 0; nt < 8; nt++)
#pragma unroll
            for (int c = 0; c < 4; c++) acc[mt][nt][c] = 0.f;

    int nkc = K >> 5;
    ISSUE_CHUNK(0, 0);
    for (int kc = 0; kc < nkc; kc++) {
        int st = kc & 1;
        if (kc + 1 < nkc) {
            ISSUE_CHUNK(kc + 1, st ^ 1);
            asm volatile("cp.async.wait_group 1;");
        } else {
            asm volatile("cp.async.wait_group 0;");
        }
        __syncthreads();

        const float* As_ = gsm + st * 9216;
        const float* Bs_ = As_ + 4608;
        int lq = lane >> 2, lr = lane & 3;
#pragma unroll
        for (int ks = 0; ks < 4; ks++) {
            int kb = ks * 8 + lr;
            uint32_t af[2][4], bf[8][2];
#pragma unroll
            for (int mt = 0; mt < 2; mt++) {
                int r0 = warp_m * 32 + mt * 16 + lq;
                af[mt][0] = __float_as_uint(As_[r0 * 36 + kb]);
                af[mt][1] = __float_as_uint(As_[(r0 + 8) * 36 + kb]);
                af[mt][2] = __float_as_uint(As_[r0 * 36 + kb + 4]);
                af[mt][3] = __float_as_uint(As_[(r0 + 8) * 36 + kb + 4]);
            }
#pragma unroll
            for (int nt = 0; nt < 8; nt++) {
                int nr = warp_n * 64 + nt * 8 + lq;
                bf[nt][0] = __float_as_uint(Bs_[nr * 36 + kb]);
                bf[nt][1] = __float_as_uint(Bs_[nr * 36 + kb + 4]);
            }
#pragma unroll
            for (int mt = 0; mt < 2; mt++)
#pragma unroll
                for (int nt = 0; nt < 8; nt++)
                    mma_tf32(acc[mt][nt], af[mt], bf[nt]);
        }
        __syncthreads();
    }
#undef ISSUE_CHUNK

    // ---- epilogue ----
    int lq = lane >> 2, lr = lane & 3;
    // per-mt global row bases (2 rows each: r, r+8)
    size_t gb[2][2];
#pragma unroll
    for (int mt = 0; mt < 2; mt++) {
#pragma unroll
        for (int h8 = 0; h8 < 2; h8++) {
            int m = m0 + warp_m * 32 + mt * 16 + lq + h8 * 8;
            if (mode == 1) {
                int wnd = m / LTOK, t = m - wnd * LTOK;
                int wd = wnd >> 6, wh = (wnd >> 3) & 7, ww = wnd & 7;
                int td = t / 49, r = t - td * 49, th = r / 7, tw = r - th * 7;
                int d = wd * 8 + td, h = wh * 7 + th, w = ww * 7 + tw;
                if (shifted) {
                    d = (d + 4) & 15;
                    h += 3; if (h >= 56) h -= 56;
                    w += 3; if (w >= 56) w -= 56;
                }
                gb[mt][h8] = (size_t)((d * 56 + h) * 56 + w) * CCH;
            } else {
                gb[mt][h8] = (size_t)m * (mode == 0 ? 384 : (mode == 2 ? HIDDIM : CCH));
            }
        }
    }

#pragma unroll
    for (int mt = 0; mt < 2; mt++) {
#pragma unroll
        for (int nt = 0; nt < 8; nt++) {
            int col = n0 + warp_n * 64 + nt * 8 + lr * 2;
            float b0 = bias[col], b1 = bias[col + 1];
#pragma unroll
            for (int h8 = 0; h8 < 2; h8++) {
                float v0 = acc[mt][nt][h8 * 2]     + b0;
                float v1 = acc[mt][nt][h8 * 2 + 1] + b1;
                float* dst;
                if (mode == 0) {
                    if (n0 == 0) { v0 *= QK_SCALE; v1 *= QK_SCALE; }
                    dst = Cp + gb[mt][h8] + col;
                    *(float2*)dst = make_float2(v0, v1);
                } else if (mode == 1) {
                    dst = Cp + gb[mt][h8] + col;
                    float2 o = *(float2*)dst;
                    *(float2*)dst = make_float2(o.x + v0, o.y + v1);
                } else if (mode == 2) {
                    v0 = 0.5f * v0 * (1.f + erff(v0 * 0.70710678118654752f));
                    v1 = 0.5f * v1 * (1.f + erff(v1 * 0.70710678118654752f));
                    dst = Cp + gb[mt][h8] + col;
                    *(float2*)dst = make_float2(v0, v1);
                } else {
                    float2 r2 = *(const float2*)(resid + gb[mt][h8] + col);
                    dst = Cp + gb[mt][h8] + col;
                    *(float2*)dst = make_float2(r2.x + v0, r2.y + v1);
                }
            }
        }
    }
}

// ------------------------------------------------------------------
// Attention (proven R3 version): CTA = (window, head), 8 warps, 7-row chunks.
#define ATT_SMEM_FLOATS (12936 + 13440 + 22400 + 2535 + 392)
__global__ __launch_bounds__(256, 1) void attn_kernel(
    const float* __restrict__ qkv, const float* __restrict__ rpb,
    float* __restrict__ out, int use_mask)
{
    extern __shared__ float sm[];
    float* Ksh  = sm;
    float* Vt   = sm + 12936;
    float* Ps   = sm + 12936 + 13440;
    float* rpbs = sm + 12936 + 13440 + 22400;
    int*   enc  = (int*)(rpbs + TABLE);

    int wnd = blockIdx.x, head = blockIdx.y;
    int tid = threadIdx.x;
    const float* base = qkv + (size_t)wnd * LTOK * 384 + head * HDIM;

    for (int idx = tid; idx < LTOK * 32; idx += 256) {
        int m = idx >> 5, d = idx & 31;
        Ksh[m * 33 + d] = base[(size_t)m * 384 + 128 + d];
        Vt[d * 420 + m] = base[(size_t)m * 384 + 256 + d];
    }
    for (int i = tid; i < TABLE; i += 256) rpbs[i] = rpb[i * NHEAD + head];
    {
        int wd = wnd >> 6, wh = (wnd >> 3) & 7, ww = wnd & 7;
        for (int t = tid; t < LTOK; t += 256) {
            int td = t / 49, r = t - td * 49, th = r / 7, tw = r - th * 7;
            int d = wd * 8 + td, h = wh * 7 + th, w = ww * 7 + tw;
            int rd = d < 8 ? 0 : (d < 12 ? 1 : 2);
            int rh = h < 49 ? 0 : (h < 53 ? 1 : 2);
            int rw = w < 49 ? 0 : (w < 53 ? 1 : 2);
            enc[t] = ((rd * 9 + rh * 3 + rw) << 12) | (td << 8) | (th << 4) | tw;
        }
    }
    __syncthreads();

    int warp = tid >> 5, lane = tid & 31;
    float* Pw = Ps + warp * 2800;
    unsigned pw_base = s2u(Pw);
    unsigned vt_base = s2u(Vt + lane * 420);

    int moff[13], mval[13], menc[13];
#pragma unroll
    for (int i = 0; i < 13; i++) {
        int m = lane + 32 * i;
        mval[i] = (m < LTOK);
        moff[i] = (mval[i] ? m : LTOK - 1) * 33;
        menc[i] = enc[mval[i] ? m : 0];
    }

    int rbase0 = warp * 49;
    for (int c = 0; c < 7; c++) {
        int r0 = rbase0 + c * 7;
        float qreg[7];
        int rtd[7], rth[7], rtw[7], rl[7];
#pragma unroll
        for (int j = 0; j < 7; j++) {
            qreg[j] = base[(size_t)(r0 + j) * 384 + lane];
            int re = enc[r0 + j];
            rtd[j] = (re >> 8) & 15; rth[j] = (re >> 4) & 15;
            rtw[j] = re & 15; rl[j] = re >> 12;
        }
        float s[7][13];
#pragma unroll
        for (int i = 0; i < 13; i++) {
            int me = menc[i];
            int mtd = (me >> 8) & 15, mth = (me >> 4) & 15, mtw = me & 15, ml = me >> 12;
#pragma unroll
            for (int j = 0; j < 7; j++) {
                float b = rpbs[(rtd[j] - mtd + 7) * 169 + (rth[j] - mth + 6) * 13
                               + (rtw[j] - mtw + 6)];
                if (use_mask && ml != rl[j]) b -= 100.f;
                s[j][i] = mval[i] ? b : -1e30f;
            }
        }
#pragma unroll 4
        for (int d2 = 0; d2 < 32; d2++) {
            float kv[13];
#pragma unroll
            for (int i = 0; i < 13; i++) kv[i] = Ksh[moff[i] + d2];
#pragma unroll
            for (int j = 0; j < 7; j++) {
                float qb = __shfl_sync(0xffffffffu, qreg[j], d2);
#pragma unroll
                for (int i = 0; i < 13; i++) s[j][i] += qb * kv[i];
            }
        }
#pragma unroll
        for (int j = 0; j < 7; j++) {
            float mx = s[j][0];
#pragma unroll
            for (int i = 1; i < 13; i++) mx = fmaxf(mx, s[j][i]);
#pragma unroll
            for (int o = 16; o; o >>= 1) mx = fmaxf(mx, __shfl_xor_sync(0xffffffffu, mx, o));
            float sum = 0.f;
#pragma unroll
            for (int i = 0; i < 13; i++) { float e = __expf(s[j][i] - mx); s[j][i] = e; sum += e; }
#pragma unroll
            for (int o = 16; o; o >>= 1) sum += __shfl_xor_sync(0xffffffffu, sum, o);
            float inv = 1.f / sum;
#pragma unroll
            for (int i = 0; i < 13; i++)
                if (mval[i]) Pw[j * 400 + lane + 32 * i] = s[j][i] * inv;
        }
        __syncwarp();
        unsigned long long acc2[7];
#pragma unroll
        for (int j = 0; j < 7; j++) acc2[j] = 0ull;
        for (int m4 = 0; m4 < LTOK; m4 += 4) {
            unsigned long long va, vb;
            asm volatile("ld.shared.v2.b64 {%0,%1},[%2];"
                         : "=l"(va), "=l"(vb) : "r"(vt_base + m4 * 4));
#pragma unroll
            for (int j = 0; j < 7; j++) {
                unsigned long long pa, pb;
                asm volatile("ld.shared.v2.b64 {%0,%1},[%2];"
                             : "=l"(pa), "=l"(pb) : "r"(pw_base + (j * 400 + m4) * 4));
                asm("fma.rn.f32x2 %0,%1,%2,%0;" : "+l"(acc2[j]) : "l"(pa), "l"(va));
                asm("fma.rn.f32x2 %0,%1,%2,%0;" : "+l"(acc2[j]) : "l"(pb), "l"(vb));
            }
        }
#pragma unroll
        for (int j = 0; j < 7; j++) {
            float2 f = *(float2*)&acc2[j];
            out[((size_t)wnd * LTOK + r0 + j) * CCH + head * HDIM + lane] = f.x + f.y;
        }
        __syncwarp();
    }
}

// ------------------------------------------------------------------
extern "C" void kernel_launch(void* const* d_in, const int* in_sizes, int n_in,
                              void* d_out, int out_size)
{
    const float* x_in   = (const float*)d_in[0];
    const float* ln1_g  = (const float*)d_in[1];
    const float* ln1_b  = (const float*)d_in[2];
    const float* qkv_w  = (const float*)d_in[3];
    const float* qkv_b  = (const float*)d_in[4];
    const float* rpb    = (const float*)d_in[5];
    const float* proj_w = (const float*)d_in[6];
    const float* proj_b = (const float*)d_in[7];
    const float* ln2_g  = (const float*)d_in[8];
    const float* ln2_b  = (const float*)d_in[9];
    const float* fc1_w  = (const float*)d_in[10];
    const float* fc1_b  = (const float*)d_in[11];
    const float* fc2_w  = (const float*)d_in[12];
    const float* fc2_b  = (const float*)d_in[13];

    float *px, *pxw, *pqkv, *patt, *py, *phid, *pbt;
    cudaGetSymbolAddress((void**)&px,   g_x);
    cudaGetSymbolAddress((void**)&pxw,  g_xw);
    cudaGetSymbolAddress((void**)&pqkv, g_qkv);
    cudaGetSymbolAddress((void**)&patt, g_att);
    cudaGetSymbolAddress((void**)&py,   g_y);
    cudaGetSymbolAddress((void**)&phid, g_hid);
    cudaGetSymbolAddress((void**)&pbt,  g_bt);

    const int ATTN_SMEM = ATT_SMEM_FLOATS * 4;
    cudaFuncSetAttribute(attn_kernel, cudaFuncAttributeMaxDynamicSharedMemorySize, ATTN_SMEM);
    cudaFuncSetAttribute(gemm_mma_kernel, cudaFuncAttributeMaxDynamicSharedMemorySize, GEMM_SMEM);

    copy_in_kernel<<<NTOK * CCH / 256, 256>>>(x_in);

    // pre-transpose all weights to [N,K]
    dim3 tb(32, 8);
    for (int i = 0; i < 2; i++) {
        float* bt = pbt + i * 196608;
        transpose_kernel<<<dim3(4, 12),  tb>>>(qkv_w  + i * 49152, bt,          128, 384);
        transpose_kernel<<<dim3(4, 4),   tb>>>(proj_w + i * 16384, bt + 49152,  128, 128);
        transpose_kernel<<<dim3(4, 16),  tb>>>(fc1_w  + i * 65536, bt + 65536,  128, 512);
        transpose_kernel<<<dim3(16, 4),  tb>>>(fc2_w  + i * 65536, bt + 131072, 512, 128);
    }

    for (int i = 0; i < 2; i++) {
        float* bt = pbt + i * 196608;
        ln_kernel<<<NTOK / 8, 256>>>(px, ln1_g + i * 128, ln1_b + i * 128, pxw, i ? 2 : 1);
        gemm_mma_kernel<<<dim3(3, 392), 256, GEMM_SMEM>>>(
            pxw, bt, qkv_b + i * 384, pqkv, nullptr, 128, 384, 0, 0);
        attn_kernel<<<dim3(NWIN, NHEAD), 256, ATTN_SMEM>>>(
            pqkv, rpb + i * TABLE * NHEAD, patt, i);
        gemm_mma_kernel<<<dim3(1, 392), 256, GEMM_SMEM>>>(
            patt, bt + 49152, proj_b + i * 128, px, nullptr, 128, 128, 1, i);
        ln_kernel<<<NTOK / 8, 256>>>(px, ln2_g + i * 128, ln2_b + i * 128, py, 0);
        gemm_mma_kernel<<<dim3(4, 392), 256, GEMM_SMEM>>>(
            py, bt + 65536, fc1_b + i * 512, phid, nullptr, 128, 512, 2, 0);
        float* outp = (i == 1) ? (float*)d_out : px;
        gemm_mma_kernel<<<dim3(1, 392), 256, GEMM_SMEM>>>(
            phid, bt + 131072, fc2_b + i * 128, outp, px, 512, 128, 3, 0);
    }
}

// round 9
// speedup vs baseline: 3.8060x; 1.5611x over previous
#include <cuda_runtime.h>
#include <math.h>
#include <stdint.h>

#define NTOK 50176          // 16*56*56 = 392*128
#define CCH  128
#define LTOK 392
#define NWIN 128
#define NHEAD 4
#define HDIM 32
#define HIDDIM 512
#define TABLE 2535
#define QK_SCALE 0.17677669529663687f

// ---- scratch ----
__device__ __align__(16) float g_x  [NTOK * CCH];
__device__ __align__(16) float g_xw [NTOK * CCH];
__device__ __align__(16) float g_qkv[NTOK * 3 * CCH];
__device__ __align__(16) float g_att[NTOK * CCH];
__device__ __align__(16) float g_y  [NTOK * CCH];
__device__ __align__(16) float g_hid[NTOK * HIDDIM];
__device__ __align__(16) float g_bt [393216];            // transposed weights, 2 blocks
__device__ __align__(16) float g_bm [NHEAD * LTOK * LTOK]; // per-head bias matrix (2.5 MB)

// ------------------------------------------------------------------
__global__ void copy_in_kernel(const float* __restrict__ src) {
    int i = blockIdx.x * 256 + threadIdx.x;
    g_x[i] = src[i];
}

// out[n*K+k] = in[k*N+n]
__global__ void transpose_kernel(const float* __restrict__ in, float* __restrict__ out,
                                 int K, int N) {
    __shared__ float t[32][33];
    int kb = blockIdx.x * 32, nb = blockIdx.y * 32;
    int tx = threadIdx.x, ty = threadIdx.y;           // 32 x 8
    for (int r = ty; r < 32; r += 8) {
        int k = kb + r, n = nb + tx;
        t[r][tx] = (k < K && n < N) ? in[(size_t)k * N + n] : 0.f;
    }
    __syncthreads();
    for (int r = ty; r < 32; r += 8) {
        int n = nb + r, k = kb + tx;
        if (n < N && k < K) out[(size_t)n * K + k] = t[tx][r];
    }
}

// per-head relative-position-bias matrix: bm[h][r][c]
__global__ void bias_mat_kernel(const float* __restrict__ rpb, float* __restrict__ bm) {
    int rc = blockIdx.x * 256 + threadIdx.x;
    if (rc >= LTOK * LTOK) return;
    int r = rc / LTOK, c = rc - r * LTOK;
    int rtd = r / 49, rr = r - rtd * 49, rth = rr / 7, rtw = rr - rth * 7;
    int ctd = c / 49, cr = c - ctd * 49, cth = cr / 7, ctw = cr - cth * 7;
    int idx = (rtd - ctd + 7) * 169 + (rth - cth + 6) * 13 + (rtw - ctw + 6);
#pragma unroll
    for (int h = 0; h < NHEAD; h++)
        bm[h * (LTOK * LTOK) + rc] = rpb[idx * NHEAD + h];
}

// ------------------------------------------------------------------
// LayerNorm, one warp per token. mode 0 plain, 1 windowed, 2 windowed+shift.
__global__ __launch_bounds__(256) void ln_kernel(
    const float* __restrict__ x, const float* __restrict__ gw,
    const float* __restrict__ gb, float* __restrict__ out, int mode)
{
    int warp = threadIdx.x >> 5, lane = threadIdx.x & 31;
    int token = blockIdx.x * 8 + warp;
    int src;
    if (mode == 0) {
        src = token;
    } else {
        int wnd = token / LTOK, t = token - wnd * LTOK;
        int wd = wnd >> 6, wh = (wnd >> 3) & 7, ww = wnd & 7;
        int td = t / 49, r = t - td * 49, th = r / 7, tw = r - th * 7;
        int d = wd * 8 + td, h = wh * 7 + th, w = ww * 7 + tw;
        if (mode == 2) {
            d = (d + 4) & 15;
            h += 3; if (h >= 56) h -= 56;
            w += 3; if (w >= 56) w -= 56;
        }
        src = (d * 56 + h) * 56 + w;
    }
    const float* xp = x + (size_t)src * CCH;
    float v[4];
#pragma unroll
    for (int i = 0; i < 4; i++) v[i] = xp[lane + 32 * i];
    float s = v[0] + v[1] + v[2] + v[3];
#pragma unroll
    for (int o = 16; o; o >>= 1) s += __shfl_xor_sync(0xffffffffu, s, o);
    float mean = s * (1.f / 128.f);
    float q = 0.f;
#pragma unroll
    for (int i = 0; i < 4; i++) { float d0 = v[i] - mean; q += d0 * d0; }
#pragma unroll
    for (int o = 16; o; o >>= 1) q += __shfl_xor_sync(0xffffffffu, q, o);
    float inv = rsqrtf(q * (1.f / 128.f) + 1e-5f);
    float* op = out + (size_t)token * CCH;
#pragma unroll
    for (int i = 0; i < 4; i++) {
        int c = lane + 32 * i;
        op[c] = (v[i] - mean) * inv * gw[c] + gb[c];
    }
}

// ------------------------------------------------------------------
__device__ __forceinline__ unsigned s2u(const void* p) {
    unsigned a;
    asm("{ .reg .u64 t; cvta.to.shared.u64 t, %1; cvt.u32.u64 %0, t; }" : "=r"(a) : "l"(p));
    return a;
}
__device__ __forceinline__ void cp16(unsigned dst, const void* src) {
    asm volatile("cp.async.ca.shared.global [%0], [%1], 16;" :: "r"(dst), "l"(src));
}
__device__ __forceinline__ void mma_tf32(float c[4], const uint32_t a[4], const uint32_t b[2]) {
    asm volatile(
        "mma.sync.aligned.m16n8k8.row.col.f32.tf32.tf32.f32 "
        "{%0,%1,%2,%3}, {%4,%5,%6,%7}, {%8,%9}, {%0,%1,%2,%3};"
        : "+f"(c[0]), "+f"(c[1]), "+f"(c[2]), "+f"(c[3])
        : "r"(a[0]), "r"(a[1]), "r"(a[2]), "r"(a[3]), "r"(b[0]), "r"(b[1]));
}

// ------------------------------------------------------------------
// mma.sync tf32 GEMM (proven R6): C = A[M,K] @ Bt[N,K]^T + bias. 128x128/CTA.
#define GEMM_SMEM (18432 * 4)
__global__ __launch_bounds__(256, 2) void gemm_mma_kernel(
    const float* __restrict__ A, const float* __restrict__ Bt,
    const float* __restrict__ bias, float* __restrict__ Cp,
    const float* __restrict__ resid, int K, int N, int mode, int shifted)
{
    extern __shared__ float gsm[];
    int tid = threadIdx.x, wid = tid >> 5, lane = tid & 31;
    int warp_m = wid & 3, warp_n = wid >> 2;
    int m0 = blockIdx.y * 128, n0 = blockIdx.x * 128;
    unsigned smu = s2u(gsm);

    const float* Abase = A + (size_t)m0 * K;
    const float* Bbase = Bt + (size_t)n0 * K;

    int lrow = tid >> 1;
    int lk4h = (tid & 1) * 4;

#define ISSUE_CHUNK(kc, st) do {                                               \
        const float* as = Abase + (size_t)lrow * K + (kc) * 32 + lk4h * 4;     \
        const float* bs = Bbase + (size_t)lrow * K + (kc) * 32 + lk4h * 4;     \
        unsigned ad = smu + ((st) * 9216 + lrow * 36 + lk4h * 4) * 4;          \
        unsigned bd = smu + ((st) * 9216 + 4608 + lrow * 36 + lk4h * 4) * 4;   \
        cp16(ad,      as);      cp16(bd,      bs);                             \
        cp16(ad + 16, as + 4);  cp16(bd + 16, bs + 4);                         \
        cp16(ad + 32, as + 8);  cp16(bd + 32, bs + 8);                         \
        cp16(ad + 48, as + 12); cp16(bd + 48, bs + 12);                        \
        asm volatile("cp.async.commit_group;");                                \
    } while (0)

    float acc[2][8][4];
#pragma unroll
    for (int mt = 0; mt < 2; mt++)
#pragma unroll
        for (int nt = 0; nt < 8; nt++)
#pragma unroll
            for (int c = 0; c < 4; c++) acc[mt][nt][c] = 0.f;

    int nkc = K >> 5;
    ISSUE_CHUNK(0, 0);
    for (int kc = 0; kc < nkc; kc++) {
        int st = kc & 1;
        if (kc + 1 < nkc) {
            ISSUE_CHUNK(kc + 1, st ^ 1);
            asm volatile("cp.async.wait_group 1;");
        } else {
            asm volatile("cp.async.wait_group 0;");
        }
        __syncthreads();

        const float* As_ = gsm + st * 9216;
        const float* Bs_ = As_ + 4608;
        int lq = lane >> 2, lr = lane & 3;
#pragma unroll
        for (int ks = 0; ks < 4; ks++) {
            int kb = ks * 8 + lr;
            uint32_t af[2][4], bf[8][2];
#pragma unroll
            for (int mt = 0; mt < 2; mt++) {
                int r0 = warp_m * 32 + mt * 16 + lq;
                af[mt][0] = __float_as_uint(As_[r0 * 36 + kb]);
                af[mt][1] = __float_as_uint(As_[(r0 + 8) * 36 + kb]);
                af[mt][2] = __float_as_uint(As_[r0 * 36 + kb + 4]);
                af[mt][3] = __float_as_uint(As_[(r0 + 8) * 36 + kb + 4]);
            }
#pragma unroll
            for (int nt = 0; nt < 8; nt++) {
                int nr = warp_n * 64 + nt * 8 + lq;
                bf[nt][0] = __float_as_uint(Bs_[nr * 36 + kb]);
                bf[nt][1] = __float_as_uint(Bs_[nr * 36 + kb + 4]);
            }
#pragma unroll
            for (int mt = 0; mt < 2; mt++)
#pragma unroll
                for (int nt = 0; nt < 8; nt++)
                    mma_tf32(acc[mt][nt], af[mt], bf[nt]);
        }
        __syncthreads();
    }
#undef ISSUE_CHUNK

    int lq = lane >> 2, lr = lane & 3;
    size_t gb[2][2];
#pragma unroll
    for (int mt = 0; mt < 2; mt++) {
#pragma unroll
        for (int h8 = 0; h8 < 2; h8++) {
            int m = m0 + warp_m * 32 + mt * 16 + lq + h8 * 8;
            if (mode == 1) {
                int wnd = m / LTOK, t = m - wnd * LTOK;
                int wd = wnd >> 6, wh = (wnd >> 3) & 7, ww = wnd & 7;
                int td = t / 49, r = t - td * 49, th = r / 7, tw = r - th * 7;
                int d = wd * 8 + td, h = wh * 7 + th, w = ww * 7 + tw;
                if (shifted) {
                    d = (d + 4) & 15;
                    h += 3; if (h >= 56) h -= 56;
                    w += 3; if (w >= 56) w -= 56;
                }
                gb[mt][h8] = (size_t)((d * 56 + h) * 56 + w) * CCH;
            } else {
                gb[mt][h8] = (size_t)m * (mode == 0 ? 384 : (mode == 2 ? HIDDIM : CCH));
            }
        }
    }

#pragma unroll
    for (int mt = 0; mt < 2; mt++) {
#pragma unroll
        for (int nt = 0; nt < 8; nt++) {
            int col = n0 + warp_n * 64 + nt * 8 + lr * 2;
            float b0 = bias[col], b1 = bias[col + 1];
#pragma unroll
            for (int h8 = 0; h8 < 2; h8++) {
                float v0 = acc[mt][nt][h8 * 2]     + b0;
                float v1 = acc[mt][nt][h8 * 2 + 1] + b1;
                float* dst;
                if (mode == 0) {
                    if (n0 == 0) { v0 *= QK_SCALE; v1 *= QK_SCALE; }
                    dst = Cp + gb[mt][h8] + col;
                    *(float2*)dst = make_float2(v0, v1);
                } else if (mode == 1) {
                    dst = Cp + gb[mt][h8] + col;
                    float2 o = *(float2*)dst;
                    *(float2*)dst = make_float2(o.x + v0, o.y + v1);
                } else if (mode == 2) {
                    v0 = 0.5f * v0 * (1.f + erff(v0 * 0.70710678118654752f));
                    v1 = 0.5f * v1 * (1.f + erff(v1 * 0.70710678118654752f));
                    dst = Cp + gb[mt][h8] + col;
                    *(float2*)dst = make_float2(v0, v1);
                } else {
                    float2 r2 = *(const float2*)(resid + gb[mt][h8] + col);
                    dst = Cp + gb[mt][h8] + col;
                    *(float2*)dst = make_float2(r2.x + v0, r2.y + v1);
                }
            }
        }
    }
}

// ------------------------------------------------------------------
// mma.sync attention: CTA = (window, head), 8 warps, 25 m16 q-tiles (L padded
// to 400), online softmax over 7 key-blocks of 56. Conflict-free smem strides:
// K 36 (4lq+lr), Vt 396 (12lq+lr), P 60 (28lq+lr). Bias from precomputed bm.
// smem floats: Ks 392*36=14112 | Vt 32*396=12672 | P 8*16*60=7680 | lab 392
#define ATT2_SMEM ((14112 + 12672 + 7680 + 392) * 4)
__global__ __launch_bounds__(256, 1) void attn2_kernel(
    const float* __restrict__ qkv, const float* __restrict__ bm,
    float* __restrict__ out, int use_mask)
{
    extern __shared__ float sm[];
    float* Ks = sm;                       // stride 36
    float* Vt = sm + 14112;               // stride 396
    float* Ps = sm + 14112 + 12672;       // per-warp 960 (16 x 60)
    int*   lab = (int*)(sm + 14112 + 12672 + 7680);

    int wnd = blockIdx.x, head = blockIdx.y;
    int tid = threadIdx.x;
    const float* base = qkv + (size_t)wnd * LTOK * 384 + head * 32;

    for (int idx = tid; idx < LTOK * 32; idx += 256) {
        int m = idx >> 5, d = idx & 31;
        Ks[m * 36 + d]  = base[(size_t)m * 384 + 128 + d];
        Vt[d * 396 + m] = base[(size_t)m * 384 + 256 + d];
    }
    {
        int wd = wnd >> 6, wh = (wnd >> 3) & 7, ww = wnd & 7;
        for (int t = tid; t < LTOK; t += 256) {
            int td = t / 49, r = t - td * 49, th = r / 7, tw = r - th * 7;
            int d = wd * 8 + td, h = wh * 7 + th, w = ww * 7 + tw;
            int rd = d < 8 ? 0 : (d < 12 ? 1 : 2);
            int rh = h < 49 ? 0 : (h < 53 ? 1 : 2);
            int rw = w < 49 ? 0 : (w < 53 ? 1 : 2);
            lab[t] = rd * 9 + rh * 3 + rw;
        }
    }
    __syncthreads();

    int warp = tid >> 5, lane = tid & 31, lq = lane >> 2, lr = lane & 3;
    float* Pw = Ps + warp * 960;
    const float* bh = bm + (size_t)head * (LTOK * LTOK);

    for (int t = warp; t < 25; t += 8) {
        int r0 = t * 16;
        int ra = min(r0 + lq, LTOK - 1), rb = min(r0 + lq + 8, LTOK - 1);
        uint32_t qa[4][4];
#pragma unroll
        for (int ks = 0; ks < 4; ks++) {
            qa[ks][0] = __float_as_uint(base[(size_t)ra * 384 + ks * 8 + lr]);
            qa[ks][1] = __float_as_uint(base[(size_t)rb * 384 + ks * 8 + lr]);
            qa[ks][2] = __float_as_uint(base[(size_t)ra * 384 + ks * 8 + lr + 4]);
            qa[ks][3] = __float_as_uint(base[(size_t)rb * 384 + ks * 8 + lr + 4]);
        }
        int labA = lab[ra], labB = lab[rb];
        const float* bra = bh + (size_t)ra * LTOK;
        const float* brb = bh + (size_t)rb * LTOK;

        float mA = -1e30f, mB = -1e30f, lA = 0.f, lB = 0.f;
        float o[4][4];
#pragma unroll
        for (int n = 0; n < 4; n++)
#pragma unroll
            for (int c = 0; c < 4; c++) o[n][c] = 0.f;

        for (int kb = 0; kb < 7; kb++) {
            int kb0 = kb * 56;
            float s[7][4];
#pragma unroll
            for (int nt = 0; nt < 7; nt++)
                s[nt][0] = s[nt][1] = s[nt][2] = s[nt][3] = 0.f;
#pragma unroll
            for (int ks = 0; ks < 4; ks++) {
                int kd = ks * 8 + lr;
#pragma unroll
                for (int nt = 0; nt < 7; nt++) {
                    int key = kb0 + nt * 8 + lq;
                    uint32_t bf[2];
                    bf[0] = __float_as_uint(Ks[key * 36 + kd]);
                    bf[1] = __float_as_uint(Ks[key * 36 + kd + 4]);
                    mma_tf32(s[nt], qa[ks], bf);
                }
            }
            // bias + mask
#pragma unroll
            for (int nt = 0; nt < 7; nt++) {
                int c0 = kb0 + nt * 8 + 2 * lr;
                float2 ba = *(const float2*)(bra + c0);
                float2 bb = *(const float2*)(brb + c0);
                if (use_mask) {
                    int l0 = lab[c0], l1 = lab[c0 + 1];
                    if (l0 != labA) ba.x -= 100.f;
                    if (l1 != labA) ba.y -= 100.f;
                    if (l0 != labB) bb.x -= 100.f;
                    if (l1 != labB) bb.y -= 100.f;
                }
                s[nt][0] += ba.x; s[nt][1] += ba.y;
                s[nt][2] += bb.x; s[nt][3] += bb.y;
            }
            // online softmax
            float ma = -1e30f, mb = -1e30f;
#pragma unroll
            for (int nt = 0; nt < 7; nt++) {
                ma = fmaxf(ma, fmaxf(s[nt][0], s[nt][1]));
                mb = fmaxf(mb, fmaxf(s[nt][2], s[nt][3]));
            }
            ma = fmaxf(ma, __shfl_xor_sync(0xffffffffu, ma, 1));
            ma = fmaxf(ma, __shfl_xor_sync(0xffffffffu, ma, 2));
            mb = fmaxf(mb, __shfl_xor_sync(0xffffffffu, mb, 1));
            mb = fmaxf(mb, __shfl_xor_sync(0xffffffffu, mb, 2));
            float nmA = fmaxf(mA, ma), nmB = fmaxf(mB, mb);
            float scA = __expf(mA - nmA), scB = __expf(mB - nmB);
            float sA = 0.f, sB = 0.f;
#pragma unroll
            for (int nt = 0; nt < 7; nt++) {
                s[nt][0] = __expf(s[nt][0] - nmA); sA += s[nt][0];
                s[nt][1] = __expf(s[nt][1] - nmA); sA += s[nt][1];
                s[nt][2] = __expf(s[nt][2] - nmB); sB += s[nt][2];
                s[nt][3] = __expf(s[nt][3] - nmB); sB += s[nt][3];
            }
            sA += __shfl_xor_sync(0xffffffffu, sA, 1);
            sA += __shfl_xor_sync(0xffffffffu, sA, 2);
            sB += __shfl_xor_sync(0xffffffffu, sB, 1);
            sB += __shfl_xor_sync(0xffffffffu, sB, 2);
            lA = lA * scA + sA; lB = lB * scB + sB;
            mA = nmA; mB = nmB;
#pragma unroll
            for (int n = 0; n < 4; n++) {
                o[n][0] *= scA; o[n][1] *= scA;
                o[n][2] *= scB; o[n][3] *= scB;
            }
            // stage P
#pragma unroll
            for (int nt = 0; nt < 7; nt++) {
                int c = nt * 8 + 2 * lr;
                *(float2*)(Pw + lq * 60 + c)       = make_float2(s[nt][0], s[nt][1]);
                *(float2*)(Pw + (lq + 8) * 60 + c) = make_float2(s[nt][2], s[nt][3]);
            }
            __syncwarp();
            // P @ V
#pragma unroll
            for (int ks2 = 0; ks2 < 7; ks2++) {
                int pc = ks2 * 8 + lr;
                uint32_t pa[4];
                pa[0] = __float_as_uint(Pw[lq * 60 + pc]);
                pa[1] = __float_as_uint(Pw[(lq + 8) * 60 + pc]);
                pa[2] = __float_as_uint(Pw[lq * 60 + pc + 4]);
                pa[3] = __float_as_uint(Pw[(lq + 8) * 60 + pc + 4]);
#pragma unroll
                for (int ntd = 0; ntd < 4; ntd++) {
                    uint32_t bf[2];
                    int voff = (ntd * 8 + lq) * 396 + kb0 + ks2 * 8 + lr;
                    bf[0] = __float_as_uint(Vt[voff]);
                    bf[1] = __float_as_uint(Vt[voff + 4]);
                    mma_tf32(o[ntd], pa, bf);
                }
            }
            __syncwarp();
        }
        float iA = 1.f / lA, iB = 1.f / lB;
        if (r0 + lq < LTOK) {
            float* op = out + ((size_t)wnd * LTOK + r0 + lq) * CCH + head * 32;
#pragma unroll
            for (int ntd = 0; ntd < 4; ntd++)
                *(float2*)(op + ntd * 8 + 2 * lr) =
                    make_float2(o[ntd][0] * iA, o[ntd][1] * iA);
        }
        if (r0 + lq + 8 < LTOK) {
            float* op = out + ((size_t)wnd * LTOK + r0 + lq + 8) * CCH + head * 32;
#pragma unroll
            for (int ntd = 0; ntd < 4; ntd++)
                *(float2*)(op + ntd * 8 + 2 * lr) =
                    make_float2(o[ntd][2] * iB, o[ntd][3] * iB);
        }
    }
}

// ------------------------------------------------------------------
extern "C" void kernel_launch(void* const* d_in, const int* in_sizes, int n_in,
                              void* d_out, int out_size)
{
    const float* x_in   = (const float*)d_in[0];
    const float* ln1_g  = (const float*)d_in[1];
    const float* ln1_b  = (const float*)d_in[2];
    const float* qkv_w  = (const float*)d_in[3];
    const float* qkv_b  = (const float*)d_in[4];
    const float* rpb    = (const float*)d_in[5];
    const float* proj_w = (const float*)d_in[6];
    const float* proj_b = (const float*)d_in[7];
    const float* ln2_g  = (const float*)d_in[8];
    const float* ln2_b  = (const float*)d_in[9];
    const float* fc1_w  = (const float*)d_in[10];
    const float* fc1_b  = (const float*)d_in[11];
    const float* fc2_w  = (const float*)d_in[12];
    const float* fc2_b  = (const float*)d_in[13];

    float *px, *pxw, *pqkv, *patt, *py, *phid, *pbt, *pbm;
    cudaGetSymbolAddress((void**)&px,   g_x);
    cudaGetSymbolAddress((void**)&pxw,  g_xw);
    cudaGetSymbolAddress((void**)&pqkv, g_qkv);
    cudaGetSymbolAddress((void**)&patt, g_att);
    cudaGetSymbolAddress((void**)&py,   g_y);
    cudaGetSymbolAddress((void**)&phid, g_hid);
    cudaGetSymbolAddress((void**)&pbt,  g_bt);
    cudaGetSymbolAddress((void**)&pbm,  g_bm);

    cudaFuncSetAttribute(attn2_kernel, cudaFuncAttributeMaxDynamicSharedMemorySize, ATT2_SMEM);
    cudaFuncSetAttribute(gemm_mma_kernel, cudaFuncAttributeMaxDynamicSharedMemorySize, GEMM_SMEM);

    copy_in_kernel<<<NTOK * CCH / 256, 256>>>(x_in);

    // pre-transpose all weights to [N,K]
    dim3 tb(32, 8);
    for (int i = 0; i < 2; i++) {
        float* bt = pbt + i * 196608;
        transpose_kernel<<<dim3(4, 12),  tb>>>(qkv_w  + i * 49152, bt,          128, 384);
        transpose_kernel<<<dim3(4, 4),   tb>>>(proj_w + i * 16384, bt + 49152,  128, 128);
        transpose_kernel<<<dim3(4, 16),  tb>>>(fc1_w  + i * 65536, bt + 65536,  128, 512);
        transpose_kernel<<<dim3(16, 4),  tb>>>(fc2_w  + i * 65536, bt + 131072, 512, 128);
    }

    for (int i = 0; i < 2; i++) {
        float* bt = pbt + i * 196608;
        ln_kernel<<<NTOK / 8, 256>>>(px, ln1_g + i * 128, ln1_b + i * 128, pxw, i ? 2 : 1);
        gemm_mma_kernel<<<dim3(3, 392), 256, GEMM_SMEM>>>(
            pxw, bt, qkv_b + i * 384, pqkv, nullptr, 128, 384, 0, 0);
        bias_mat_kernel<<<(LTOK * LTOK + 255) / 256, 256>>>(rpb + i * TABLE * NHEAD, pbm);
        attn2_kernel<<<dim3(NWIN, NHEAD), 256, ATT2_SMEM>>>(pqkv, pbm, patt, i);
        gemm_mma_kernel<<<dim3(1, 392), 256, GEMM_SMEM>>>(
            patt, bt + 49152, proj_b + i * 128, px, nullptr, 128, 128, 1, i);
        ln_kernel<<<NTOK / 8, 256>>>(px, ln2_g + i * 128, ln2_b + i * 128, py, 0);
        gemm_mma_kernel<<<dim3(4, 392), 256, GEMM_SMEM>>>(
            py, bt + 65536, fc1_b + i * 512, phid, nullptr, 128, 512, 2, 0);
        float* outp = (i == 1) ? (float*)d_out : px;
        gemm_mma_kernel<<<dim3(1, 392), 256, GEMM_SMEM>>>(
            phid, bt + 131072, fc2_b + i * 128, outp, px, 512, 128, 3, 0);
    }
}

// round 10
// speedup vs baseline: 4.4149x; 1.1600x over previous
#include <cuda_runtime.h>
#include <math.h>
#include <stdint.h>

#define NTOK 50176          // 16*56*56 = 392*128
#define CCH  128
#define LTOK 392
#define NWIN 128
#define NHEAD 4
#define HDIM 32
#define HIDDIM 512
#define TABLE 2535
#define QK_SCALE 0.17677669529663687f

// ---- scratch ----
__device__ __align__(16) float g_x  [NTOK * CCH];
__device__ __align__(16) float g_xw [NTOK * CCH];
__device__ __align__(16) float g_qkv[NTOK * 3 * CCH];
__device__ __align__(16) float g_att[NTOK * CCH];
__device__ __align__(16) float g_y  [NTOK * CCH];
__device__ __align__(16) float g_hid[NTOK * HIDDIM];
__device__ __align__(16) float g_bt [393216];            // transposed weights, 2 blocks
__device__ __align__(16) float g_bm [NHEAD * LTOK * LTOK]; // per-head bias matrix (2.5 MB)

// ------------------------------------------------------------------
__global__ void copy_in_kernel(const float* __restrict__ src) {
    int i = blockIdx.x * 256 + threadIdx.x;
    g_x[i] = src[i];
}

// fused weight transpose: 384 tiles over both blocks' 4 matrices
__global__ void transpose_all_kernel(const float* __restrict__ qkv_w,
                                     const float* __restrict__ proj_w,
                                     const float* __restrict__ fc1_w,
                                     const float* __restrict__ fc2_w,
                                     float* __restrict__ bt_all) {
    __shared__ float t[32][33];
    int b = blockIdx.x;
    int i = b / 192, r = b % 192;
    const float* src; float* dst; int K, N, Kt, idx;
    if (r < 48)       { src = qkv_w  + i * 49152; dst = bt_all + i * 196608;          K = 128; N = 384; Kt = 4;  idx = r; }
    else if (r < 64)  { src = proj_w + i * 16384; dst = bt_all + i * 196608 + 49152;  K = 128; N = 128; Kt = 4;  idx = r - 48; }
    else if (r < 128) { src = fc1_w  + i * 65536; dst = bt_all + i * 196608 + 65536;  K = 128; N = 512; Kt = 4;  idx = r - 64; }
    else              { src = fc2_w  + i * 65536; dst = bt_all + i * 196608 + 131072; K = 512; N = 128; Kt = 16; idx = r - 128; }
    int kb = (idx % Kt) * 32, nb = (idx / Kt) * 32;
    int tx = threadIdx.x, ty = threadIdx.y;           // 32 x 8
    for (int rr = ty; rr < 32; rr += 8)
        t[rr][tx] = src[(size_t)(kb + rr) * N + nb + tx];
    __syncthreads();
    for (int rr = ty; rr < 32; rr += 8)
        dst[(size_t)(nb + rr) * K + kb + tx] = t[tx][rr];
}

// per-head relative-position-bias matrix: bm[h][r][c]
__global__ void bias_mat_kernel(const float* __restrict__ rpb, float* __restrict__ bm) {
    int rc = blockIdx.x * 256 + threadIdx.x;
    if (rc >= LTOK * LTOK) return;
    int r = rc / LTOK, c = rc - r * LTOK;
    int rtd = r / 49, rr = r - rtd * 49, rth = rr / 7, rtw = rr - rth * 7;
    int ctd = c / 49, cr = c - ctd * 49, cth = cr / 7, ctw = cr - cth * 7;
    int idx = (rtd - ctd + 7) * 169 + (rth - cth + 6) * 13 + (rtw - ctw + 6);
#pragma unroll
    for (int h = 0; h < NHEAD; h++)
        bm[h * (LTOK * LTOK) + rc] = rpb[idx * NHEAD + h];
}

// ------------------------------------------------------------------
// LayerNorm, one warp per token. mode 0 plain, 1 windowed, 2 windowed+shift.
__global__ __launch_bounds__(256) void ln_kernel(
    const float* __restrict__ x, const float* __restrict__ gw,
    const float* __restrict__ gb, float* __restrict__ out, int mode)
{
    int warp = threadIdx.x >> 5, lane = threadIdx.x & 31;
    int token = blockIdx.x * 8 + warp;
    int src;
    if (mode == 0) {
        src = token;
    } else {
        int wnd = token / LTOK, t = token - wnd * LTOK;
        int wd = wnd >> 6, wh = (wnd >> 3) & 7, ww = wnd & 7;
        int td = t / 49, r = t - td * 49, th = r / 7, tw = r - th * 7;
        int d = wd * 8 + td, h = wh * 7 + th, w = ww * 7 + tw;
        if (mode == 2) {
            d = (d + 4) & 15;
            h += 3; if (h >= 56) h -= 56;
            w += 3; if (w >= 56) w -= 56;
        }
        src = (d * 56 + h) * 56 + w;
    }
    const float* xp = x + (size_t)src * CCH;
    float v[4];
#pragma unroll
    for (int i = 0; i < 4; i++) v[i] = xp[lane + 32 * i];
    float s = v[0] + v[1] + v[2] + v[3];
#pragma unroll
    for (int o = 16; o; o >>= 1) s += __shfl_xor_sync(0xffffffffu, s, o);
    float mean = s * (1.f / 128.f);
    float q = 0.f;
#pragma unroll
    for (int i = 0; i < 4; i++) { float d0 = v[i] - mean; q += d0 * d0; }
#pragma unroll
    for (int o = 16; o; o >>= 1) q += __shfl_xor_sync(0xffffffffu, q, o);
    float inv = rsqrtf(q * (1.f / 128.f) + 1e-5f);
    float* op = out + (size_t)token * CCH;
#pragma unroll
    for (int i = 0; i < 4; i++) {
        int c = lane + 32 * i;
        op[c] = (v[i] - mean) * inv * gw[c] + gb[c];
    }
}

// ------------------------------------------------------------------
__device__ __forceinline__ unsigned s2u(const void* p) {
    unsigned a;
    asm("{ .reg .u64 t; cvta.to.shared.u64 t, %1; cvt.u32.u64 %0, t; }" : "=r"(a) : "l"(p));
    return a;
}
__device__ __forceinline__ void cp16(unsigned dst, const void* src) {
    asm volatile("cp.async.ca.shared.global [%0], [%1], 16;" :: "r"(dst), "l"(src));
}
__device__ __forceinline__ void mma_tf32(float c[4], const uint32_t a[4], const uint32_t b[2]) {
    asm volatile(
        "mma.sync.aligned.m16n8k8.row.col.f32.tf32.tf32.f32 "
        "{%0,%1,%2,%3}, {%4,%5,%6,%7}, {%8,%9}, {%0,%1,%2,%3};"
        : "+f"(c[0]), "+f"(c[1]), "+f"(c[2]), "+f"(c[3])
        : "r"(a[0]), "r"(a[1]), "r"(a[2]), "r"(a[3]), "r"(b[0]), "r"(b[1]));
}

// ------------------------------------------------------------------
// mma.sync tf32 GEMM (proven R6): C = A[M,K] @ Bt[N,K]^T + bias. 128x128/CTA.
#define GEMM_SMEM (18432 * 4)
__global__ __launch_bounds__(256, 2) void gemm_mma_kernel(
    const float* __restrict__ A, const float* __restrict__ Bt,
    const float* __restrict__ bias, float* __restrict__ Cp,
    const float* __restrict__ resid, int K, int N, int mode, int shifted)
{
    extern __shared__ float gsm[];
    int tid = threadIdx.x, wid = tid >> 5, lane = tid & 31;
    int warp_m = wid & 3, warp_n = wid >> 2;
    int m0 = blockIdx.y * 128, n0 = blockIdx.x * 128;
    unsigned smu = s2u(gsm);

    const float* Abase = A + (size_t)m0 * K;
    const float* Bbase = Bt + (size_t)n0 * K;

    int lrow = tid >> 1;
    int lk4h = (tid & 1) * 4;

#define ISSUE_CHUNK(kc, st) do {                                               \
        const float* as = Abase + (size_t)lrow * K + (kc) * 32 + lk4h * 4;     \
        const float* bs = Bbase + (size_t)lrow * K + (kc) * 32 + lk4h * 4;     \
        unsigned ad = smu + ((st) * 9216 + lrow * 36 + lk4h * 4) * 4;          \
        unsigned bd = smu + ((st) * 9216 + 4608 + lrow * 36 + lk4h * 4) * 4;   \
        cp16(ad,      as);      cp16(bd,      bs);                             \
        cp16(ad + 16, as + 4);  cp16(bd + 16, bs + 4);                         \
        cp16(ad + 32, as + 8);  cp16(bd + 32, bs + 8);                         \
        cp16(ad + 48, as + 12); cp16(bd + 48, bs + 12);                        \
        asm volatile("cp.async.commit_group;");                                \
    } while (0)

    float acc[2][8][4];
#pragma unroll
    for (int mt = 0; mt < 2; mt++)
#pragma unroll
        for (int nt = 0; nt < 8; nt++)
#pragma unroll
            for (int c = 0; c < 4; c++) acc[mt][nt][c] = 0.f;

    int nkc = K >> 5;
    ISSUE_CHUNK(0, 0);
    for (int kc = 0; kc < nkc; kc++) {
        int st = kc & 1;
        if (kc + 1 < nkc) {
            ISSUE_CHUNK(kc + 1, st ^ 1);
            asm volatile("cp.async.wait_group 1;");
        } else {
            asm volatile("cp.async.wait_group 0;");
        }
        __syncthreads();

        const float* As_ = gsm + st * 9216;
        const float* Bs_ = As_ + 4608;
        int lq = lane >> 2, lr = lane & 3;
#pragma unroll
        for (int ks = 0; ks < 4; ks++) {
            int kb = ks * 8 + lr;
            uint32_t af[2][4], bf[8][2];
#pragma unroll
            for (int mt = 0; mt < 2; mt++) {
                int r0 = warp_m * 32 + mt * 16 + lq;
                af[mt][0] = __float_as_uint(As_[r0 * 36 + kb]);
                af[mt][1] = __float_as_uint(As_[(r0 + 8) * 36 + kb]);
                af[mt][2] = __float_as_uint(As_[r0 * 36 + kb + 4]);
                af[mt][3] = __float_as_uint(As_[(r0 + 8) * 36 + kb + 4]);
            }
#pragma unroll
            for (int nt = 0; nt < 8; nt++) {
                int nr = warp_n * 64 + nt * 8 + lq;
                bf[nt][0] = __float_as_uint(Bs_[nr * 36 + kb]);
                bf[nt][1] = __float_as_uint(Bs_[nr * 36 + kb + 4]);
            }
#pragma unroll
            for (int mt = 0; mt < 2; mt++)
#pragma unroll
                for (int nt = 0; nt < 8; nt++)
                    mma_tf32(acc[mt][nt], af[mt], bf[nt]);
        }
        __syncthreads();
    }
#undef ISSUE_CHUNK

    int lq = lane >> 2, lr = lane & 3;
    size_t gb[2][2];
#pragma unroll
    for (int mt = 0; mt < 2; mt++) {
#pragma unroll
        for (int h8 = 0; h8 < 2; h8++) {
            int m = m0 + warp_m * 32 + mt * 16 + lq + h8 * 8;
            if (mode == 1) {
                int wnd = m / LTOK, t = m - wnd * LTOK;
                int wd = wnd >> 6, wh = (wnd >> 3) & 7, ww = wnd & 7;
                int td = t / 49, r = t - td * 49, th = r / 7, tw = r - th * 7;
                int d = wd * 8 + td, h = wh * 7 + th, w = ww * 7 + tw;
                if (shifted) {
                    d = (d + 4) & 15;
                    h += 3; if (h >= 56) h -= 56;
                    w += 3; if (w >= 56) w -= 56;
                }
                gb[mt][h8] = (size_t)((d * 56 + h) * 56 + w) * CCH;
            } else {
                gb[mt][h8] = (size_t)m * (mode == 0 ? 384 : (mode == 2 ? HIDDIM : CCH));
            }
        }
    }

#pragma unroll
    for (int mt = 0; mt < 2; mt++) {
#pragma unroll
        for (int nt = 0; nt < 8; nt++) {
            int col = n0 + warp_n * 64 + nt * 8 + lr * 2;
            float b0 = bias[col], b1 = bias[col + 1];
#pragma unroll
            for (int h8 = 0; h8 < 2; h8++) {
                float v0 = acc[mt][nt][h8 * 2]     + b0;
                float v1 = acc[mt][nt][h8 * 2 + 1] + b1;
                float* dst;
                if (mode == 0) {
                    if (n0 == 0) { v0 *= QK_SCALE; v1 *= QK_SCALE; }
                    dst = Cp + gb[mt][h8] + col;
                    *(float2*)dst = make_float2(v0, v1);
                } else if (mode == 1) {
                    dst = Cp + gb[mt][h8] + col;
                    float2 o = *(float2*)dst;
                    *(float2*)dst = make_float2(o.x + v0, o.y + v1);
                } else if (mode == 2) {
                    v0 = 0.5f * v0 * (1.f + erff(v0 * 0.70710678118654752f));
                    v1 = 0.5f * v1 * (1.f + erff(v1 * 0.70710678118654752f));
                    dst = Cp + gb[mt][h8] + col;
                    *(float2*)dst = make_float2(v0, v1);
                } else {
                    float2 r2 = *(const float2*)(resid + gb[mt][h8] + col);
                    dst = Cp + gb[mt][h8] + col;
                    *(float2*)dst = make_float2(r2.x + v0, r2.y + v1);
                }
            }
        }
    }
}

// ------------------------------------------------------------------
// attn3: mma.sync attention, 2 CTAs/SM. No P smem (shuffle transpose),
// no running max (S bounded; masked -100 underflows to exact 0), l-reduce
// deferred to once per q-tile.
// smem floats: Ks 392*36=14112 | Vt 32*396=12672 | lab 392  -> 108704 B
#define ATT3_SMEM ((14112 + 12672 + 392) * 4)
__global__ __launch_bounds__(256, 2) void attn3_kernel(
    const float* __restrict__ qkv, const float* __restrict__ bm,
    float* __restrict__ out, int use_mask)
{
    extern __shared__ float sm[];
    float* Ks = sm;                       // stride 36
    float* Vt = sm + 14112;               // stride 396
    int*   lab = (int*)(sm + 14112 + 12672);

    int wnd = blockIdx.x, head = blockIdx.y;
    int tid = threadIdx.x;
    const float* base = qkv + (size_t)wnd * LTOK * 384 + head * 32;

    for (int idx = tid; idx < LTOK * 32; idx += 256) {
        int m = idx >> 5, d = idx & 31;
        Ks[m * 36 + d]  = base[(size_t)m * 384 + 128 + d];
        Vt[d * 396 + m] = base[(size_t)m * 384 + 256 + d];
    }
    {
        int wd = wnd >> 6, wh = (wnd >> 3) & 7, ww = wnd & 7;
        for (int t = tid; t < LTOK; t += 256) {
            int td = t / 49, r = t - td * 49, th = r / 7, tw = r - th * 7;
            int d = wd * 8 + td, h = wh * 7 + th, w = ww * 7 + tw;
            int rd = d < 8 ? 0 : (d < 12 ? 1 : 2);
            int rh = h < 49 ? 0 : (h < 53 ? 1 : 2);
            int rw = w < 49 ? 0 : (w < 53 ? 1 : 2);
            lab[t] = rd * 9 + rh * 3 + rw;
        }
    }
    __syncthreads();

    int warp = tid >> 5, lane = tid & 31, lq = lane >> 2, lr = lane & 3;
    const float* bh = bm + (size_t)head * (LTOK * LTOK);
    int psrc0 = lq * 4 + (lr >> 1);       // shuffle src for P col lr
    int psel  = lr & 1;

    for (int t = warp; t < 25; t += 8) {
        int r0 = t * 16;
        int ra = min(r0 + lq, LTOK - 1), rb = min(r0 + lq + 8, LTOK - 1);
        uint32_t qa[4][4];
#pragma unroll
        for (int ks = 0; ks < 4; ks++) {
            qa[ks][0] = __float_as_uint(base[(size_t)ra * 384 + ks * 8 + lr]);
            qa[ks][1] = __float_as_uint(base[(size_t)rb * 384 + ks * 8 + lr]);
            qa[ks][2] = __float_as_uint(base[(size_t)ra * 384 + ks * 8 + lr + 4]);
            qa[ks][3] = __float_as_uint(base[(size_t)rb * 384 + ks * 8 + lr + 4]);
        }
        int labA = lab[ra], labB = lab[rb];
        const float* bra = bh + (size_t)ra * LTOK;
        const float* brb = bh + (size_t)rb * LTOK;

        float lA = 0.f, lB = 0.f;
        float o[4][4];
#pragma unroll
        for (int n = 0; n < 4; n++)
#pragma unroll
            for (int c = 0; c < 4; c++) o[n][c] = 0.f;

        for (int kb = 0; kb < 7; kb++) {
            int kb0 = kb * 56;
            float s[7][4];
#pragma unroll
            for (int nt = 0; nt < 7; nt++)
                s[nt][0] = s[nt][1] = s[nt][2] = s[nt][3] = 0.f;
#pragma unroll
            for (int ks = 0; ks < 4; ks++) {
                int kd = ks * 8 + lr;
#pragma unroll
                for (int nt = 0; nt < 7; nt++) {
                    int key = kb0 + nt * 8 + lq;
                    uint32_t bf[2];
                    bf[0] = __float_as_uint(Ks[key * 36 + kd]);
                    bf[1] = __float_as_uint(Ks[key * 36 + kd + 4]);
                    mma_tf32(s[nt], qa[ks], bf);
                }
            }
            // bias + mask + exp + partial sums (no max: S bounded, -100 -> 0)
#pragma unroll
            for (int nt = 0; nt < 7; nt++) {
                int c0 = kb0 + nt * 8 + 2 * lr;
                float2 ba = *(const float2*)(bra + c0);
                float2 bb = *(const float2*)(brb + c0);
                if (use_mask) {
                    int l0 = lab[c0], l1 = lab[c0 + 1];
                    if (l0 != labA) ba.x -= 100.f;
                    if (l1 != labA) ba.y -= 100.f;
                    if (l0 != labB) bb.x -= 100.f;
                    if (l1 != labB) bb.y -= 100.f;
                }
                s[nt][0] = __expf(s[nt][0] + ba.x); lA += s[nt][0];
                s[nt][1] = __expf(s[nt][1] + ba.y); lA += s[nt][1];
                s[nt][2] = __expf(s[nt][2] + bb.x); lB += s[nt][2];
                s[nt][3] = __expf(s[nt][3] + bb.y); lB += s[nt][3];
            }
            // P @ V: shuffle-transpose c-layout -> a-frags
#pragma unroll
            for (int ks2 = 0; ks2 < 7; ks2++) {
                uint32_t pa[4];
                {
                    float x0 = __shfl_sync(0xffffffffu, s[ks2][0], psrc0, 4);
                    float x1 = __shfl_sync(0xffffffffu, s[ks2][1], psrc0, 4);
                    pa[0] = __float_as_uint(psel ? x1 : x0);
                    float y0 = __shfl_sync(0xffffffffu, s[ks2][2], psrc0, 4);
                    float y1 = __shfl_sync(0xffffffffu, s[ks2][3], psrc0, 4);
                    pa[1] = __float_as_uint(psel ? y1 : y0);
                    float z0 = __shfl_sync(0xffffffffu, s[ks2][0], psrc0 + 2, 4);
                    float z1 = __shfl_sync(0xffffffffu, s[ks2][1], psrc0 + 2, 4);
                    pa[2] = __float_as_uint(psel ? z1 : z0);
                    float w0 = __shfl_sync(0xffffffffu, s[ks2][2], psrc0 + 2, 4);
                    float w1 = __shfl_sync(0xffffffffu, s[ks2][3], psrc0 + 2, 4);
                    pa[3] = __float_as_uint(psel ? w1 : w0);
                }
#pragma unroll
                for (int ntd = 0; ntd < 4; ntd++) {
                    uint32_t bf[2];
                    int voff = (ntd * 8 + lq) * 396 + kb0 + ks2 * 8 + lr;
                    bf[0] = __float_as_uint(Vt[voff]);
                    bf[1] = __float_as_uint(Vt[voff + 4]);
                    mma_tf32(o[ntd], pa, bf);
                }
            }
        }
        // one l-reduce per q-tile
        lA += __shfl_xor_sync(0xffffffffu, lA, 1);
        lA += __shfl_xor_sync(0xffffffffu, lA, 2);
        lB += __shfl_xor_sync(0xffffffffu, lB, 1);
        lB += __shfl_xor_sync(0xffffffffu, lB, 2);
        float iA = 1.f / lA, iB = 1.f / lB;
        if (r0 + lq < LTOK) {
            float* op = out + ((size_t)wnd * LTOK + r0 + lq) * CCH + head * 32;
#pragma unroll
            for (int ntd = 0; ntd < 4; ntd++)
                *(float2*)(op + ntd * 8 + 2 * lr) =
                    make_float2(o[ntd][0] * iA, o[ntd][1] * iA);
        }
        if (r0 + lq + 8 < LTOK) {
            float* op = out + ((size_t)wnd * LTOK + r0 + lq + 8) * CCH + head * 32;
#pragma unroll
            for (int ntd = 0; ntd < 4; ntd++)
                *(float2*)(op + ntd * 8 + 2 * lr) =
                    make_float2(o[ntd][2] * iB, o[ntd][3] * iB);
        }
    }
}

// ------------------------------------------------------------------
extern "C" void kernel_launch(void* const* d_in, const int* in_sizes, int n_in,
                              void* d_out, int out_size)
{
    const float* x_in   = (const float*)d_in[0];
    const float* ln1_g  = (const float*)d_in[1];
    const float* ln1_b  = (const float*)d_in[2];
    const float* qkv_w  = (const float*)d_in[3];
    const float* qkv_b  = (const float*)d_in[4];
    const float* rpb    = (const float*)d_in[5];
    const float* proj_w = (const float*)d_in[6];
    const float* proj_b = (const float*)d_in[7];
    const float* ln2_g  = (const float*)d_in[8];
    const float* ln2_b  = (const float*)d_in[9];
    const float* fc1_w  = (const float*)d_in[10];
    const float* fc1_b  = (const float*)d_in[11];
    const float* fc2_w  = (const float*)d_in[12];
    const float* fc2_b  = (const float*)d_in[13];

    float *px, *pxw, *pqkv, *patt, *py, *phid, *pbt, *pbm;
    cudaGetSymbolAddress((void**)&px,   g_x);
    cudaGetSymbolAddress((void**)&pxw,  g_xw);
    cudaGetSymbolAddress((void**)&pqkv, g_qkv);
    cudaGetSymbolAddress((void**)&patt, g_att);
    cudaGetSymbolAddress((void**)&py,   g_y);
    cudaGetSymbolAddress((void**)&phid, g_hid);
    cudaGetSymbolAddress((void**)&pbt,  g_bt);
    cudaGetSymbolAddress((void**)&pbm,  g_bm);

    cudaFuncSetAttribute(attn3_kernel, cudaFuncAttributeMaxDynamicSharedMemorySize, ATT3_SMEM);
    cudaFuncSetAttribute(gemm_mma_kernel, cudaFuncAttributeMaxDynamicSharedMemorySize, GEMM_SMEM);

    copy_in_kernel<<<NTOK * CCH / 256, 256>>>(x_in);
    transpose_all_kernel<<<384, dim3(32, 8)>>>(qkv_w, proj_w, fc1_w, fc2_w, pbt);

    for (int i = 0; i < 2; i++) {
        float* bt = pbt + i * 196608;
        ln_kernel<<<NTOK / 8, 256>>>(px, ln1_g + i * 128, ln1_b + i * 128, pxw, i ? 2 : 1);
        gemm_mma_kernel<<<dim3(3, 392), 256, GEMM_SMEM>>>(
            pxw, bt, qkv_b + i * 384, pqkv, nullptr, 128, 384, 0, 0);
        bias_mat_kernel<<<(LTOK * LTOK + 255) / 256, 256>>>(rpb + i * TABLE * NHEAD, pbm);
        attn3_kernel<<<dim3(NWIN, NHEAD), 256, ATT3_SMEM>>>(pqkv, pbm, patt, i);
        gemm_mma_kernel<<<dim3(1, 392), 256, GEMM_SMEM>>>(
            patt, bt + 49152, proj_b + i * 128, px, nullptr, 128, 128, 1, i);
        ln_kernel<<<NTOK / 8, 256>>>(px, ln2_g + i * 128, ln2_b + i * 128, py, 0);
        gemm_mma_kernel<<<dim3(4, 392), 256, GEMM_SMEM>>>(
            py, bt + 65536, fc1_b + i * 512, phid, nullptr, 128, 512, 2, 0);
        float* outp = (i == 1) ? (float*)d_out : px;
        gemm_mma_kernel<<<dim3(1, 392), 256, GEMM_SMEM>>>(
            phid, bt + 131072, fc2_b + i * 128, outp, px, 512, 128, 3, 0);
    }
}

// round 15
// speedup vs baseline: 6.4257x; 1.4555x over previous
#include <cuda_runtime.h>
#include <cuda_bf16.h>
#include <math.h>
#include <stdint.h>

#define NTOK 50176          // 16*56*56 = 392*128
#define CCH  128
#define LTOK 392
#define NWIN 128
#define NHEAD 4
#define HIDDIM 512
#define TABLE 2535
#define QK_SCALE 0.17677669529663687f

// ---- scratch ----
__device__ __align__(16) float g_x  [NTOK * CCH];              // residual, fp32
__device__ __align__(16) float g_qkv[NTOK * 3 * CCH];          // qkv, fp32
__device__ __align__(16) __nv_bfloat16 gb_xw [NTOK * CCH];     // LN1 out
__device__ __align__(16) __nv_bfloat16 gb_att[NTOK * CCH];     // attn out
__device__ __align__(16) __nv_bfloat16 gb_y  [NTOK * CCH];     // LN2 out
__device__ __align__(16) __nv_bfloat16 gb_hid[NTOK * HIDDIM];  // GELU out
__device__ __align__(16) __nv_bfloat16 gb_bt [393216];         // transposed weights
__device__ __align__(16) float g_bm [NHEAD * LTOK * LTOK];     // bias matrix

// ------------------------------------------------------------------
__device__ __forceinline__ unsigned s2u(const void* p) {
    unsigned a;
    asm("{ .reg .u64 t; cvta.to.shared.u64 t, %1; cvt.u32.u64 %0, t; }" : "=r"(a) : "l"(p));
    return a;
}
__device__ __forceinline__ void cp16(unsigned dst, const void* src) {
    asm volatile("cp.async.ca.shared.global [%0], [%1], 16;" :: "r"(dst), "l"(src));
}
__device__ __forceinline__ uint32_t packbf(float lo, float hi) {
    uint32_t r;
    asm("cvt.rn.bf16x2.f32 %0, %1, %2;" : "=r"(r) : "f"(hi), "f"(lo));
    return r;
}
__device__ __forceinline__ void mma_bf16(float c[4], const uint32_t a[4], const uint32_t b[2]) {
    asm volatile(
        "mma.sync.aligned.m16n8k16.row.col.f32.bf16.bf16.f32 "
        "{%0,%1,%2,%3}, {%4,%5,%6,%7}, {%8,%9}, {%0,%1,%2,%3};"
        : "+f"(c[0]), "+f"(c[1]), "+f"(c[2]), "+f"(c[3])
        : "r"(a[0]), "r"(a[1]), "r"(a[2]), "r"(a[3]), "r"(b[0]), "r"(b[1]));
}

// ------------------------------------------------------------------
__global__ void copy_in_kernel(const float* __restrict__ src) {
    int i = blockIdx.x * 256 + threadIdx.x;
    g_x[i] = src[i];
}

// fused weight transpose -> bf16 [N][K]
__global__ void transpose_all_kernel(const float* __restrict__ qkv_w,
                                     const float* __restrict__ proj_w,
                                     const float* __restrict__ fc1_w,
                                     const float* __restrict__ fc2_w,
                                     __nv_bfloat16* __restrict__ bt_all) {
    __shared__ float t[32][33];
    int b = blockIdx.x;
    int i = b / 192, r = b % 192;
    const float* src; __nv_bfloat16* dst; int K, N, Kt, idx;
    if (r < 48)       { src = qkv_w  + i * 49152; dst = bt_all + i * 196608;          K = 128; N = 384; Kt = 4;  idx = r; }
    else if (r < 64)  { src = proj_w + i * 16384; dst = bt_all + i * 196608 + 49152;  K = 128; N = 128; Kt = 4;  idx = r - 48; }
    else if (r < 128) { src = fc1_w  + i * 65536; dst = bt_all + i * 196608 + 65536;  K = 128; N = 512; Kt = 4;  idx = r - 64; }
    else              { src = fc2_w  + i * 65536; dst = bt_all + i * 196608 + 131072; K = 512; N = 128; Kt = 16; idx = r - 128; }
    int kb = (idx % Kt) * 32, nb = (idx / Kt) * 32;
    int tx = threadIdx.x, ty = threadIdx.y;
    for (int rr = ty; rr < 32; rr += 8)
        t[rr][tx] = src[(size_t)(kb + rr) * N + nb + tx];
    __syncthreads();
    for (int rr = ty; rr < 32; rr += 8)
        dst[(size_t)(nb + rr) * K + kb + tx] = __float2bfloat16(t[tx][rr]);
}

// per-head relative-position-bias matrix: bm[h][r][c]
__global__ void bias_mat_kernel(const float* __restrict__ rpb, float* __restrict__ bm) {
    int rc = blockIdx.x * 256 + threadIdx.x;
    if (rc >= LTOK * LTOK) return;
    int r = rc / LTOK, c = rc - r * LTOK;
    int rtd = r / 49, rr = r - rtd * 49, rth = rr / 7, rtw = rr - rth * 7;
    int ctd = c / 49, cr = c - ctd * 49, cth = cr / 7, ctw = cr - cth * 7;
    int idx = (rtd - ctd + 7) * 169 + (rth - cth + 6) * 13 + (rtw - ctw + 6);
#pragma unroll
    for (int h = 0; h < NHEAD; h++)
        bm[h * (LTOK * LTOK) + rc] = rpb[idx * NHEAD + h];
}

// ------------------------------------------------------------------
// LayerNorm -> bf16 out. mode 0 plain, 1 windowed, 2 windowed+shift.
__global__ __launch_bounds__(256) void ln_kernel(
    const float* __restrict__ x, const float* __restrict__ gw,
    const float* __restrict__ gb, __nv_bfloat16* __restrict__ out, int mode)
{
    int warp = threadIdx.x >> 5, lane = threadIdx.x & 31;
    int token = blockIdx.x * 8 + warp;
    int src;
    if (mode == 0) {
        src = token;
    } else {
        int wnd = token / LTOK, t = token - wnd * LTOK;
        int wd = wnd >> 6, wh = (wnd >> 3) & 7, ww = wnd & 7;
        int td = t / 49, r = t - td * 49, th = r / 7, tw = r - th * 7;
        int d = wd * 8 + td, h = wh * 7 + th, w = ww * 7 + tw;
        if (mode == 2) {
            d = (d + 4) & 15;
            h += 3; if (h >= 56) h -= 56;
            w += 3; if (w >= 56) w -= 56;
        }
        src = (d * 56 + h) * 56 + w;
    }
    const float2* xp2 = (const float2*)(x + (size_t)src * CCH);
    float2 va = xp2[lane], vb = xp2[lane + 32];
    float s = va.x + va.y + vb.x + vb.y;
#pragma unroll
    for (int o = 16; o; o >>= 1) s += __shfl_xor_sync(0xffffffffu, s, o);
    float mean = s * (1.f / 128.f);
    float q = (va.x - mean) * (va.x - mean) + (va.y - mean) * (va.y - mean)
            + (vb.x - mean) * (vb.x - mean) + (vb.y - mean) * (vb.y - mean);
#pragma unroll
    for (int o = 16; o; o >>= 1) q += __shfl_xor_sync(0xffffffffu, q, o);
    float inv = rsqrtf(q * (1.f / 128.f) + 1e-5f);
    const float2* g2 = (const float2*)gw;
    const float2* b2 = (const float2*)gb;
    float2 ga = g2[lane], gc = g2[lane + 32];
    float2 ba = b2[lane], bc = b2[lane + 32];
    uint32_t* op = (uint32_t*)(out + (size_t)token * CCH);
    op[lane]      = packbf((va.x - mean) * inv * ga.x + ba.x,
                           (va.y - mean) * inv * ga.y + ba.y);
    op[lane + 32] = packbf((vb.x - mean) * inv * gc.x + bc.x,
                           (vb.y - mean) * inv * gc.y + bc.y);
}

// ------------------------------------------------------------------
// bf16 mma.sync GEMM: C[M,N] = A[M,K] @ Bt[N,K]^T + bias. 128x128/CTA,
// 8 warps 4x2, warp tile 32x64 (2x8 m16n8k16). BK=32, cp.async double buffer,
// bf16 smem stride 40 elems (conflict-free: 20*lq+lr bijective mod 32).
// mode 0 QKV->fp32 s384 (scale n0==0) | 1 proj scatter+resid fp32
// mode 2 GELU->bf16 s512 | 3 resid fp32 s128
#define GEMM_SMEM 40960    // 2 stages * 10240 elems * 2B
__global__ __launch_bounds__(256, 2) void gemm_mma_kernel(
    const __nv_bfloat16* __restrict__ A, const __nv_bfloat16* __restrict__ Bt,
    const float* __restrict__ bias, void* __restrict__ Cp,
    const float* __restrict__ resid, int K, int N, int mode, int shifted)
{
    extern __shared__ __nv_bfloat16 gsm[];
    int tid = threadIdx.x, wid = tid >> 5, lane = tid & 31;
    int warp_m = wid & 3, warp_n = wid >> 2;
    int m0 = blockIdx.y * 128, n0 = blockIdx.x * 128;
    unsigned smu = s2u(gsm);

    const __nv_bfloat16* Abase = A + (size_t)m0 * K;
    const __nv_bfloat16* Bbase = Bt + (size_t)n0 * K;

    int lrow = tid >> 1;             // 0..127
    int lh   = (tid & 1) * 16;       // elem 0 or 16

#define ISSUE_CHUNK(kc, st) do {                                              \
        const __nv_bfloat16* as = Abase + (size_t)lrow * K + (kc) * 32 + lh;  \
        const __nv_bfloat16* bs = Bbase + (size_t)lrow * K + (kc) * 32 + lh;  \
        unsigned ad = smu + ((st) * 10240 + lrow * 40 + lh) * 2;              \
        unsigned bd = smu + ((st) * 10240 + 5120 + lrow * 40 + lh) * 2;       \
        cp16(ad, as); cp16(ad + 16, as + 8);                                  \
        cp16(bd, bs); cp16(bd + 16, bs + 8);                                  \
        asm volatile("cp.async.commit_group;");                               \
    } while (0)

    float acc[2][8][4];
#pragma unroll
    for (int mt = 0; mt < 2; mt++)
#pragma unroll
        for (int nt = 0; nt < 8; nt++)
#pragma unroll
            for (int c = 0; c < 4; c++) acc[mt][nt][c] = 0.f;

    int nkc = K >> 5;
    ISSUE_CHUNK(0, 0);
    for (int kc = 0; kc < nkc; kc++) {
        int st = kc & 1;
        if (kc + 1 < nkc) {
            ISSUE_CHUNK(kc + 1, st ^ 1);
            asm volatile("cp.async.wait_group 1;");
        } else {
            asm volatile("cp.async.wait_group 0;");
        }
        __syncthreads();

        const uint32_t* SW = (const uint32_t*)gsm + st * 5120;
        int lq = lane >> 2, lr = lane & 3;
#pragma unroll
        for (int ks = 0; ks < 2; ks++) {
            int kw = ks * 8 + lr;
            uint32_t af[2][4], bf[8][2];
#pragma unroll
            for (int mt = 0; mt < 2; mt++) {
                int rw = (warp_m * 32 + mt * 16 + lq) * 20 + kw;
                af[mt][0] = SW[rw];
                af[mt][1] = SW[rw + 160];
                af[mt][2] = SW[rw + 4];
                af[mt][3] = SW[rw + 164];
            }
#pragma unroll
            for (int nt = 0; nt < 8; nt++) {
                int nw = 2560 + (warp_n * 64 + nt * 8 + lq) * 20 + kw;
                bf[nt][0] = SW[nw];
                bf[nt][1] = SW[nw + 4];
            }
#pragma unroll
            for (int mt = 0; mt < 2; mt++)
#pragma unroll
                for (int nt = 0; nt < 8; nt++)
                    mma_bf16(acc[mt][nt], af[mt], bf[nt]);
        }
        __syncthreads();
    }
#undef ISSUE_CHUNK

    int lq = lane >> 2, lr = lane & 3;
    size_t gb[2][2];
#pragma unroll
    for (int mt = 0; mt < 2; mt++) {
#pragma unroll
        for (int h8 = 0; h8 < 2; h8++) {
            int m = m0 + warp_m * 32 + mt * 16 + lq + h8 * 8;
            if (mode == 1) {
                int wnd = m / LTOK, t = m - wnd * LTOK;
                int wd = wnd >> 6, wh = (wnd >> 3) & 7, ww = wnd & 7;
                int td = t / 49, r = t - td * 49, th = r / 7, tw = r - th * 7;
                int d = wd * 8 + td, h = wh * 7 + th, w = ww * 7 + tw;
                if (shifted) {
                    d = (d + 4) & 15;
                    h += 3; if (h >= 56) h -= 56;
                    w += 3; if (w >= 56) w -= 56;
                }
                gb[mt][h8] = (size_t)((d * 56 + h) * 56 + w) * CCH;
            } else {
                gb[mt][h8] = (size_t)m * (mode == 0 ? 384 : (mode == 2 ? HIDDIM : CCH));
            }
        }
    }

#pragma unroll
    for (int mt = 0; mt < 2; mt++) {
#pragma unroll
        for (int nt = 0; nt < 8; nt++) {
            int col = n0 + warp_n * 64 + nt * 8 + lr * 2;
            float b0 = bias[col], b1 = bias[col + 1];
#pragma unroll
            for (int h8 = 0; h8 < 2; h8++) {
                float v0 = acc[mt][nt][h8 * 2]     + b0;
                float v1 = acc[mt][nt][h8 * 2 + 1] + b1;
                if (mode == 0) {
                    if (n0 == 0) { v0 *= QK_SCALE; v1 *= QK_SCALE; }
                    *(float2*)((float*)Cp + gb[mt][h8] + col) = make_float2(v0, v1);
                } else if (mode == 1) {
                    float* dst = (float*)Cp + gb[mt][h8] + col;
                    float2 o = *(float2*)dst;
                    *(float2*)dst = make_float2(o.x + v0, o.y + v1);
                } else if (mode == 2) {
                    v0 = 0.5f * v0 * (1.f + erff(v0 * 0.70710678118654752f));
                    v1 = 0.5f * v1 * (1.f + erff(v1 * 0.70710678118654752f));
                    ((uint32_t*)Cp)[(gb[mt][h8] + col) >> 1] = packbf(v0, v1);
                } else {
                    float2 r2 = *(const float2*)(resid + gb[mt][h8] + col);
                    *(float2*)((float*)Cp + gb[mt][h8] + col) =
                        make_float2(r2.x + v0, r2.y + v1);
                }
            }
        }
    }
}

// ------------------------------------------------------------------
// attn4: bf16 m16n8k16 attention. QK c-frags feed PV a-frags directly
// (pair-pack, zero shuffles). K smem stride 40 elems; Vt stride 392
// (196 = 4 mod 32 -> conflict-free). No running max (S bounded).
// smem: Ks 392*40*2=31360 | Vt 32*392*2=25088 | lab 392*4=1568 -> 58016 B
#define ATT4_SMEM 58016
__global__ __launch_bounds__(256, 2) void attn4_kernel(
    const float* __restrict__ qkv, const float* __restrict__ bm,
    __nv_bfloat16* __restrict__ out, int use_mask)
{
    extern __shared__ char smc[];
    __nv_bfloat16* Ksb = (__nv_bfloat16*)smc;
    __nv_bfloat16* Vtb = (__nv_bfloat16*)(smc + 31360);
    int* lab = (int*)(smc + 56448);

    int wnd = blockIdx.x, head = blockIdx.y;
    int tid = threadIdx.x;
    const float* base = qkv + (size_t)wnd * LTOK * 384 + head * 32;

    for (int idx = tid; idx < LTOK * 32; idx += 256) {
        int m = idx >> 5, d = idx & 31;
        Ksb[m * 40 + d]  = __float2bfloat16(base[(size_t)m * 384 + 128 + d]);
        Vtb[d * 392 + m] = __float2bfloat16(base[(size_t)m * 384 + 256 + d]);
    }
    {
        int wd = wnd >> 6, wh = (wnd >> 3) & 7, ww = wnd & 7;
        for (int t = tid; t < LTOK; t += 256) {
            int td = t / 49, r = t - td * 49, th = r / 7, tw = r - th * 7;
            int d = wd * 8 + td, h = wh * 7 + th, w = ww * 7 + tw;
            int rd = d < 8 ? 0 : (d < 12 ? 1 : 2);
            int rh = h < 49 ? 0 : (h < 53 ? 1 : 2);
            int rw = w < 49 ? 0 : (w < 53 ? 1 : 2);
            lab[t] = rd * 9 + rh * 3 + rw;
        }
    }
    __syncthreads();

    int warp = tid >> 5, lane = tid & 31, lq = lane >> 2, lr = lane & 3;
    const float* bh = bm + (size_t)head * (LTOK * LTOK);
    const uint32_t* Ksw = (const uint32_t*)smc;
    const uint32_t* Vtw = (const uint32_t*)(smc + 31360);

    for (int t = warp; t < 25; t += 8) {
        int r0 = t * 16;
        int ra = min(r0 + lq, LTOK - 1), rb = min(r0 + lq + 8, LTOK - 1);
        uint32_t qa[2][4];
#pragma unroll
        for (int ks = 0; ks < 2; ks++) {
            float2 a0 = *(const float2*)(base + (size_t)ra * 384 + ks * 16 + 2 * lr);
            float2 a1 = *(const float2*)(base + (size_t)rb * 384 + ks * 16 + 2 * lr);
            float2 a2 = *(const float2*)(base + (size_t)ra * 384 + ks * 16 + 8 + 2 * lr);
            float2 a3 = *(const float2*)(base + (size_t)rb * 384 + ks * 16 + 8 + 2 * lr);
            qa[ks][0] = packbf(a0.x, a0.y);
            qa[ks][1] = packbf(a1.x, a1.y);
            qa[ks][2] = packbf(a2.x, a2.y);
            qa[ks][3] = packbf(a3.x, a3.y);
        }
        int labA = lab[ra], labB = lab[rb];
        const float* bra = bh + (size_t)ra * LTOK;
        const float* brb = bh + (size_t)rb * LTOK;

        float lA = 0.f, lB = 0.f;
        float o[4][4];
#pragma unroll
        for (int n = 0; n < 4; n++)
#pragma unroll
            for (int c = 0; c < 4; c++) o[n][c] = 0.f;

        for (int kb = 0; kb < 7; kb++) {
            int kb0 = kb * 56;
            float s[7][4];
#pragma unroll
            for (int nt = 0; nt < 7; nt++)
                s[nt][0] = s[nt][1] = s[nt][2] = s[nt][3] = 0.f;
#pragma unroll
            for (int ks = 0; ks < 2; ks++) {
                int kw = ks * 8 + lr;
#pragma unroll
                for (int nt = 0; nt < 7; nt++) {
                    int nwb = (kb0 + nt * 8 + lq) * 20 + kw;
                    uint32_t bf[2];
                    bf[0] = Ksw[nwb];
                    bf[1] = Ksw[nwb + 4];
                    mma_bf16(s[nt], qa[ks], bf);
                }
            }
            // bias + mask + exp + partial sums
#pragma unroll
            for (int nt = 0; nt < 7; nt++) {
                int c0 = kb0 + nt * 8 + 2 * lr;
                float2 ba = *(const float2*)(bra + c0);
                float2 bb = *(const float2*)(brb + c0);
                if (use_mask) {
                    int l0 = lab[c0], l1 = lab[c0 + 1];
                    if (l0 != labA) ba.x -= 100.f;
                    if (l1 != labA) ba.y -= 100.f;
                    if (l0 != labB) bb.x -= 100.f;
                    if (l1 != labB) bb.y -= 100.f;
                }
                s[nt][0] = __expf(s[nt][0] + ba.x); lA += s[nt][0];
                s[nt][1] = __expf(s[nt][1] + ba.y); lA += s[nt][1];
                s[nt][2] = __expf(s[nt][2] + bb.x); lB += s[nt][2];
                s[nt][3] = __expf(s[nt][3] + bb.y); lB += s[nt][3];
            }
            // P @ V: c-frag pairs pack directly into k16 a-frags
#pragma unroll
            for (int kp = 0; kp < 4; kp++) {
                uint32_t pa[4];
                pa[0] = packbf(s[2 * kp][0], s[2 * kp][1]);
                pa[1] = packbf(s[2 * kp][2], s[2 * kp][3]);
                if (kp < 3) {
                    pa[2] = packbf(s[2 * kp + 1][0], s[2 * kp + 1][1]);
                    pa[3] = packbf(s[2 * kp + 1][2], s[2 * kp + 1][3]);
                } else {
                    pa[2] = 0u; pa[3] = 0u;
                }
                int kwv = 28 * kb + 8 * kp + lr;
#pragma unroll
                for (int ntd = 0; ntd < 4; ntd++) {
                    int vw = (ntd * 8 + lq) * 196 + kwv;
                    uint32_t bf[2];
                    bf[0] = Vtw[vw];
                    bf[1] = Vtw[vw + 4];
                    mma_bf16(o[ntd], pa, bf);
                }
            }
        }
        lA += __shfl_xor_sync(0xffffffffu, lA, 1);
        lA += __shfl_xor_sync(0xffffffffu, lA, 2);
        lB += __shfl_xor_sync(0xffffffffu, lB, 1);
        lB += __shfl_xor_sync(0xffffffffu, lB, 2);
        float iA = 1.f / lA, iB = 1.f / lB;
        if (r0 + lq < LTOK) {
            uint32_t* op = (uint32_t*)out
                + ((size_t)(wnd * LTOK + r0 + lq) * CCH + head * 32) / 2;
#pragma unroll
            for (int ntd = 0; ntd < 4; ntd++)
                op[ntd * 4 + lr] = packbf(o[ntd][0] * iA, o[ntd][1] * iA);
        }
        if (r0 + lq + 8 < LTOK) {
            uint32_t* op = (uint32_t*)out
                + ((size_t)(wnd * LTOK + r0 + lq + 8) * CCH + head * 32) / 2;
#pragma unroll
            for (int ntd = 0; ntd < 4; ntd++)
                op[ntd * 4 + lr] = packbf(o[ntd][2] * iB, o[ntd][3] * iB);
        }
    }
}

// ------------------------------------------------------------------
extern "C" void kernel_launch(void* const* d_in, const int* in_sizes, int n_in,
                              void* d_out, int out_size)
{
    const float* x_in   = (const float*)d_in[0];
    const float* ln1_g  = (const float*)d_in[1];
    const float* ln1_b  = (const float*)d_in[2];
    const float* qkv_w  = (const float*)d_in[3];
    const float* qkv_b  = (const float*)d_in[4];
    const float* rpb    = (const float*)d_in[5];
    const float* proj_w = (const float*)d_in[6];
    const float* proj_b = (const float*)d_in[7];
    const float* ln2_g  = (const float*)d_in[8];
    const float* ln2_b  = (const float*)d_in[9];
    const float* fc1_w  = (const float*)d_in[10];
    const float* fc1_b  = (const float*)d_in[11];
    const float* fc2_w  = (const float*)d_in[12];
    const float* fc2_b  = (const float*)d_in[13];

    float *px, *pqkv, *pbm;
    __nv_bfloat16 *pxw, *patt, *py, *phid, *pbt;
    cudaGetSymbolAddress((void**)&px,   g_x);
    cudaGetSymbolAddress((void**)&pqkv, g_qkv);
    cudaGetSymbolAddress((void**)&pbm,  g_bm);
    cudaGetSymbolAddress((void**)&pxw,  gb_xw);
    cudaGetSymbolAddress((void**)&patt, gb_att);
    cudaGetSymbolAddress((void**)&py,   gb_y);
    cudaGetSymbolAddress((void**)&phid, gb_hid);
    cudaGetSymbolAddress((void**)&pbt,  gb_bt);

    cudaFuncSetAttribute(attn4_kernel, cudaFuncAttributeMaxDynamicSharedMemorySize, ATT4_SMEM);
    cudaFuncSetAttribute(gemm_mma_kernel, cudaFuncAttributeMaxDynamicSharedMemorySize, GEMM_SMEM);

    copy_in_kernel<<<NTOK * CCH / 256, 256>>>(x_in);
    transpose_all_kernel<<<384, dim3(32, 8)>>>(qkv_w, proj_w, fc1_w, fc2_w, pbt);

    for (int i = 0; i < 2; i++) {
        __nv_bfloat16* bt = pbt + i * 196608;
        ln_kernel<<<NTOK / 8, 256>>>(px, ln1_g + i * 128, ln1_b + i * 128, pxw, i ? 2 : 1);
        gemm_mma_kernel<<<dim3(3, 392), 256, GEMM_SMEM>>>(
            pxw, bt, qkv_b + i * 384, pqkv, nullptr, 128, 384, 0, 0);
        bias_mat_kernel<<<(LTOK * LTOK + 255) / 256, 256>>>(rpb + i * TABLE * NHEAD, pbm);
        attn4_kernel<<<dim3(NWIN, NHEAD), 256, ATT4_SMEM>>>(pqkv, pbm, patt, i);
        gemm_mma_kernel<<<dim3(1, 392), 256, GEMM_SMEM>>>(
            patt, bt + 49152, proj_b + i * 128, px, nullptr, 128, 128, 1, i);
        ln_kernel<<<NTOK / 8, 256>>>(px, ln2_g + i * 128, ln2_b + i * 128, py, 0);
        gemm_mma_kernel<<<dim3(4, 392), 256, GEMM_SMEM>>>(
            py, bt + 65536, fc1_b + i * 512, phid, nullptr, 128, 512, 2, 0);
        gemm_mma_kernel<<<dim3(1, 392), 256, GEMM_SMEM>>>(
            phid, bt + 131072, fc2_b + i * 128,
            (i == 1) ? d_out : (void*)px, px, 512, 128, 3, 0);
    }
}

// round 17
// speedup vs baseline: 7.2555x; 1.1291x over previous
#include <cuda_runtime.h>
#include <cuda_bf16.h>
#include <math.h>
#include <stdint.h>

#define NTOK 50176          // 16*56*56 = 392*128
#define CCH  128
#define LTOK 392
#define NWIN 128
#define NHEAD 4
#define HIDDIM 512
#define TABLE 2535
#define QK_SCALE 0.17677669529663687f

// ---- scratch ----
__device__ __align__(16) float g_x  [NTOK * CCH];              // residual, fp32
__device__ __align__(16) float g_qkv[NTOK * 3 * CCH];          // qkv, fp32
__device__ __align__(16) __nv_bfloat16 gb_xw [NTOK * CCH];     // LN1 out
__device__ __align__(16) __nv_bfloat16 gb_att[NTOK * CCH];     // attn out
__device__ __align__(16) __nv_bfloat16 gb_y  [NTOK * CCH];     // LN2 out
__device__ __align__(16) __nv_bfloat16 gb_hid[NTOK * HIDDIM];  // GELU out
__device__ __align__(16) __nv_bfloat16 gb_bt [393216];         // transposed weights
__device__ __align__(16) float g_bm [NHEAD * LTOK * LTOK];     // bias matrix

// ------------------------------------------------------------------
__device__ __forceinline__ unsigned s2u(const void* p) {
    unsigned a;
    asm("{ .reg .u64 t; cvta.to.shared.u64 t, %1; cvt.u32.u64 %0, t; }" : "=r"(a) : "l"(p));
    return a;
}
__device__ __forceinline__ void cp16(unsigned dst, const void* src) {
    asm volatile("cp.async.ca.shared.global [%0], [%1], 16;" :: "r"(dst), "l"(src));
}
__device__ __forceinline__ uint32_t packbf(float lo, float hi) {
    uint32_t r;
    asm("cvt.rn.bf16x2.f32 %0, %1, %2;" : "=r"(r) : "f"(hi), "f"(lo));
    return r;
}
__device__ __forceinline__ void mma_bf16(float c[4], const uint32_t a[4], const uint32_t b[2]) {
    asm volatile(
        "mma.sync.aligned.m16n8k16.row.col.f32.bf16.bf16.f32 "
        "{%0,%1,%2,%3}, {%4,%5,%6,%7}, {%8,%9}, {%0,%1,%2,%3};"
        : "+f"(c[0]), "+f"(c[1]), "+f"(c[2]), "+f"(c[3])
        : "r"(a[0]), "r"(a[1]), "r"(a[2]), "r"(a[3]), "r"(b[0]), "r"(b[1]));
}
#define LDSM4(r0, r1, r2, r3, addr)                                           \
    asm volatile("ldmatrix.sync.aligned.m8n8.x4.shared.b16 {%0,%1,%2,%3}, [%4];" \
                 : "=r"(r0), "=r"(r1), "=r"(r2), "=r"(r3) : "r"(addr))
#define LDSM2(r0, r1, addr)                                                   \
    asm volatile("ldmatrix.sync.aligned.m8n8.x2.shared.b16 {%0,%1}, [%2];"    \
                 : "=r"(r0), "=r"(r1) : "r"(addr))

// ------------------------------------------------------------------
// fused weight transpose -> bf16 [N][K]
__global__ void transpose_all_kernel(const float* __restrict__ qkv_w,
                                     const float* __restrict__ proj_w,
                                     const float* __restrict__ fc1_w,
                                     const float* __restrict__ fc2_w,
                                     __nv_bfloat16* __restrict__ bt_all) {
    __shared__ float t[32][33];
    int b = blockIdx.x;
    int i = b / 192, r = b % 192;
    const float* src; __nv_bfloat16* dst; int K, N, Kt, idx;
    if (r < 48)       { src = qkv_w  + i * 49152; dst = bt_all + i * 196608;          K = 128; N = 384; Kt = 4;  idx = r; }
    else if (r < 64)  { src = proj_w + i * 16384; dst = bt_all + i * 196608 + 49152;  K = 128; N = 128; Kt = 4;  idx = r - 48; }
    else if (r < 128) { src = fc1_w  + i * 65536; dst = bt_all + i * 196608 + 65536;  K = 128; N = 512; Kt = 4;  idx = r - 64; }
    else              { src = fc2_w  + i * 65536; dst = bt_all + i * 196608 + 131072; K = 512; N = 128; Kt = 16; idx = r - 128; }
    int kb = (idx % Kt) * 32, nb = (idx / Kt) * 32;
    int tx = threadIdx.x, ty = threadIdx.y;
    for (int rr = ty; rr < 32; rr += 8)
        t[rr][tx] = src[(size_t)(kb + rr) * N + nb + tx];
    __syncthreads();
    for (int rr = ty; rr < 32; rr += 8)
        dst[(size_t)(nb + rr) * K + kb + tx] = __float2bfloat16(t[tx][rr]);
}

// per-head relative-position-bias matrix: bm[h][r][c]
__global__ void bias_mat_kernel(const float* __restrict__ rpb, float* __restrict__ bm) {
    int rc = blockIdx.x * 256 + threadIdx.x;
    if (rc >= LTOK * LTOK) return;
    int r = rc / LTOK, c = rc - r * LTOK;
    int rtd = r / 49, rr = r - rtd * 49, rth = rr / 7, rtw = rr - rth * 7;
    int ctd = c / 49, cr = c - ctd * 49, cth = cr / 7, ctw = cr - cth * 7;
    int idx = (rtd - ctd + 7) * 169 + (rth - cth + 6) * 13 + (rtw - ctw + 6);
#pragma unroll
    for (int h = 0; h < NHEAD; h++)
        bm[h * (LTOK * LTOK) + rc] = rpb[idx * NHEAD + h];
}

// ------------------------------------------------------------------
// LayerNorm -> bf16 out. mode 0 plain, 1 windowed, 2 windowed+shift.
__global__ __launch_bounds__(256) void ln_kernel(
    const float* __restrict__ x, const float* __restrict__ gw,
    const float* __restrict__ gb, __nv_bfloat16* __restrict__ out, int mode)
{
    int warp = threadIdx.x >> 5, lane = threadIdx.x & 31;
    int token = blockIdx.x * 8 + warp;
    int src;
    if (mode == 0) {
        src = token;
    } else {
        int wnd = token / LTOK, t = token - wnd * LTOK;
        int wd = wnd >> 6, wh = (wnd >> 3) & 7, ww = wnd & 7;
        int td = t / 49, r = t - td * 49, th = r / 7, tw = r - th * 7;
        int d = wd * 8 + td, h = wh * 7 + th, w = ww * 7 + tw;
        if (mode == 2) {
            d = (d + 4) & 15;
            h += 3; if (h >= 56) h -= 56;
            w += 3; if (w >= 56) w -= 56;
        }
        src = (d * 56 + h) * 56 + w;
    }
    const float2* xp2 = (const float2*)(x + (size_t)src * CCH);
    float2 va = xp2[lane], vb = xp2[lane + 32];
    float s = va.x + va.y + vb.x + vb.y;
#pragma unroll
    for (int o = 16; o; o >>= 1) s += __shfl_xor_sync(0xffffffffu, s, o);
    float mean = s * (1.f / 128.f);
    float q = (va.x - mean) * (va.x - mean) + (va.y - mean) * (va.y - mean)
            + (vb.x - mean) * (vb.x - mean) + (vb.y - mean) * (vb.y - mean);
#pragma unroll
    for (int o = 16; o; o >>= 1) q += __shfl_xor_sync(0xffffffffu, q, o);
    float inv = rsqrtf(q * (1.f / 128.f) + 1e-5f);
    const float2* g2 = (const float2*)gw;
    const float2* b2 = (const float2*)gb;
    float2 ga = g2[lane], gc = g2[lane + 32];
    float2 ba = b2[lane], bc = b2[lane + 32];
    uint32_t* op = (uint32_t*)(out + (size_t)token * CCH);
    op[lane]      = packbf((va.x - mean) * inv * ga.x + ba.x,
                           (va.y - mean) * inv * ga.y + ba.y);
    op[lane + 32] = packbf((vb.x - mean) * inv * gc.x + bc.x,
                           (vb.y - mean) * inv * gc.y + bc.y);
}

// ------------------------------------------------------------------
// bf16 mma.sync GEMM with ldmatrix fragment loads.
// C[M,N] = A[M,K] @ Bt[N,K]^T + bias. 128x128/CTA, warp tile 32x64.
// smem stride 40 elems (80 B rows: LDSM rows at 20r mod 32 -> conflict-free).
// mode 0 QKV->fp32 s384 (scale n0==0) | 1 proj scatter: Cp[loc]=resid[loc]+v
// mode 2 GELU->bf16 s512 | 3 resid fp32 s128
#define GEMM_SMEM 40960    // 2 stages * 10240 elems * 2B
__global__ __launch_bounds__(256, 2) void gemm_mma_kernel(
    const __nv_bfloat16* __restrict__ A, const __nv_bfloat16* __restrict__ Bt,
    const float* __restrict__ bias, void* __restrict__ Cp,
    const float* __restrict__ resid, int K, int N, int mode, int shifted)
{
    extern __shared__ __nv_bfloat16 gsm[];
    int tid = threadIdx.x, wid = tid >> 5, lane = tid & 31;
    int warp_m = wid & 3, warp_n = wid >> 2;
    int m0 = blockIdx.y * 128, n0 = blockIdx.x * 128;
    unsigned smu = s2u(gsm);

    const __nv_bfloat16* Abase = A + (size_t)m0 * K;
    const __nv_bfloat16* Bbase = Bt + (size_t)n0 * K;

    int lrow = tid >> 1;
    int lh   = (tid & 1) * 16;

#define ISSUE_CHUNK(kc, st) do {                                              \
        const __nv_bfloat16* as = Abase + (size_t)lrow * K + (kc) * 32 + lh;  \
        const __nv_bfloat16* bs = Bbase + (size_t)lrow * K + (kc) * 32 + lh;  \
        unsigned ad = smu + ((st) * 10240 + lrow * 40 + lh) * 2;              \
        unsigned bd = smu + ((st) * 10240 + 5120 + lrow * 40 + lh) * 2;       \
        cp16(ad, as); cp16(ad + 16, as + 8);                                  \
        cp16(bd, bs); cp16(bd + 16, bs + 8);                                  \
        asm volatile("cp.async.commit_group;");                               \
    } while (0)

    float acc[2][8][4];
#pragma unroll
    for (int mt = 0; mt < 2; mt++)
#pragma unroll
        for (int nt = 0; nt < 8; nt++)
#pragma unroll
            for (int c = 0; c < 4; c++) acc[mt][nt][c] = 0.f;

    // ldmatrix per-thread address components
    unsigned aoff = (unsigned)((warp_m * 32 + (lane & 15)) * 80 + (lane >> 4) * 16);
    unsigned boff = (unsigned)(10240 +
        (warp_n * 64 + (lane >> 4) * 8 + (lane & 7)) * 80 + ((lane >> 3) & 1) * 16);

    int nkc = K >> 5;
    ISSUE_CHUNK(0, 0);
    for (int kc = 0; kc < nkc; kc++) {
        int st = kc & 1;
        if (kc + 1 < nkc) {
            ISSUE_CHUNK(kc + 1, st ^ 1);
            asm volatile("cp.async.wait_group 1;");
        } else {
            asm volatile("cp.async.wait_group 0;");
        }
        __syncthreads();

        unsigned sst = smu + st * 20480u;
#pragma unroll
        for (int ks = 0; ks < 2; ks++) {
            uint32_t af[2][4], bf[8][2];
#pragma unroll
            for (int mt = 0; mt < 2; mt++)
                LDSM4(af[mt][0], af[mt][1], af[mt][2], af[mt][3],
                      sst + aoff + mt * 1280 + ks * 32);
#pragma unroll
            for (int p = 0; p < 4; p++)
                LDSM4(bf[2 * p][0], bf[2 * p][1], bf[2 * p + 1][0], bf[2 * p + 1][1],
                      sst + boff + p * 1280 + ks * 32);
#pragma unroll
            for (int mt = 0; mt < 2; mt++)
#pragma unroll
                for (int nt = 0; nt < 8; nt++)
                    mma_bf16(acc[mt][nt], af[mt], bf[nt]);
        }
        __syncthreads();
    }
#undef ISSUE_CHUNK

    int lq = lane >> 2, lr = lane & 3;
    size_t gb[2][2];
#pragma unroll
    for (int mt = 0; mt < 2; mt++) {
#pragma unroll
        for (int h8 = 0; h8 < 2; h8++) {
            int m = m0 + warp_m * 32 + mt * 16 + lq + h8 * 8;
            if (mode == 1) {
                int wnd = m / LTOK, t = m - wnd * LTOK;
                int wd = wnd >> 6, wh = (wnd >> 3) & 7, ww = wnd & 7;
                int td = t / 49, r = t - td * 49, th = r / 7, tw = r - th * 7;
                int d = wd * 8 + td, h = wh * 7 + th, w = ww * 7 + tw;
                if (shifted) {
                    d = (d + 4) & 15;
                    h += 3; if (h >= 56) h -= 56;
                    w += 3; if (w >= 56) w -= 56;
                }
                gb[mt][h8] = (size_t)((d * 56 + h) * 56 + w) * CCH;
            } else {
                gb[mt][h8] = (size_t)m * (mode == 0 ? 384 : (mode == 2 ? HIDDIM : CCH));
            }
        }
    }

#pragma unroll
    for (int mt = 0; mt < 2; mt++) {
#pragma unroll
        for (int nt = 0; nt < 8; nt++) {
            int col = n0 + warp_n * 64 + nt * 8 + lr * 2;
            float b0 = bias[col], b1 = bias[col + 1];
#pragma unroll
            for (int h8 = 0; h8 < 2; h8++) {
                float v0 = acc[mt][nt][h8 * 2]     + b0;
                float v1 = acc[mt][nt][h8 * 2 + 1] + b1;
                if (mode == 0) {
                    if (n0 == 0) { v0 *= QK_SCALE; v1 *= QK_SCALE; }
                    *(float2*)((float*)Cp + gb[mt][h8] + col) = make_float2(v0, v1);
                } else if (mode == 1) {
                    float2 r2 = *(const float2*)(resid + gb[mt][h8] + col);
                    *(float2*)((float*)Cp + gb[mt][h8] + col) =
                        make_float2(r2.x + v0, r2.y + v1);
                } else if (mode == 2) {
                    v0 = 0.5f * v0 * (1.f + erff(v0 * 0.70710678118654752f));
                    v1 = 0.5f * v1 * (1.f + erff(v1 * 0.70710678118654752f));
                    ((uint32_t*)Cp)[(gb[mt][h8] + col) >> 1] = packbf(v0, v1);
                } else {
                    float2 r2 = *(const float2*)(resid + gb[mt][h8] + col);
                    *(float2*)((float*)Cp + gb[mt][h8] + col) =
                        make_float2(r2.x + v0, r2.y + v1);
                }
            }
        }
    }
}

// ------------------------------------------------------------------
// attn5: bf16 m16n8k16 attention with ldmatrix K/V loads.
// K stride 40 elems (80 B); Vt stride 392 elems (784 B, rows 4r mod 32).
// QK c-frags feed PV a-frags directly. No running max (S bounded).
// smem: Ks 392*40*2=31360 | Vt 32*392*2=25088 | lab 392*4=1568 -> 58016 B
#define ATT5_SMEM 58016
__global__ __launch_bounds__(256, 2) void attn5_kernel(
    const float* __restrict__ qkv, const float* __restrict__ bm,
    __nv_bfloat16* __restrict__ out, int use_mask)
{
    extern __shared__ char smc[];
    __nv_bfloat16* Ksb = (__nv_bfloat16*)smc;
    __nv_bfloat16* Vtb = (__nv_bfloat16*)(smc + 31360);
    int* lab = (int*)(smc + 56448);

    int wnd = blockIdx.x, head = blockIdx.y;
    int tid = threadIdx.x;
    const float* base = qkv + (size_t)wnd * LTOK * 384 + head * 32;

    for (int idx = tid; idx < LTOK * 32; idx += 256) {
        int m = idx >> 5, d = idx & 31;
        Ksb[m * 40 + d]  = __float2bfloat16(base[(size_t)m * 384 + 128 + d]);
        Vtb[d * 392 + m] = __float2bfloat16(base[(size_t)m * 384 + 256 + d]);
    }
    {
        int wd = wnd >> 6, wh = (wnd >> 3) & 7, ww = wnd & 7;
        for (int t = tid; t < LTOK; t += 256) {
            int td = t / 49, r = t - td * 49, th = r / 7, tw = r - th * 7;
            int d = wd * 8 + td, h = wh * 7 + th, w = ww * 7 + tw;
            int rd = d < 8 ? 0 : (d < 12 ? 1 : 2);
            int rh = h < 49 ? 0 : (h < 53 ? 1 : 2);
            int rw = w < 49 ? 0 : (w < 53 ? 1 : 2);
            lab[t] = rd * 9 + rh * 3 + rw;
        }
    }
    __syncthreads();

    int warp = tid >> 5, lane = tid & 31, lq = lane >> 2, lr = lane & 3;
    const float* bh = bm + (size_t)head * (LTOK * LTOK);
    unsigned smuK = s2u(smc);
    unsigned smuV = smuK + 31360;
    // ldmatrix per-thread address components
    unsigned koff = (unsigned)(((lane >> 4) * 8 + (lane & 7)) * 80 + ((lane >> 3) & 1) * 16);
    unsigned koff2 = (unsigned)((lane & 7) * 80 + ((lane >> 3) & 1) * 16);  // x2, nt6
    unsigned voff = (unsigned)(((lane >> 4) * 8 + (lane & 7)) * 784 + ((lane >> 3) & 1) * 16);

    for (int t = warp; t < 25; t += 8) {
        int r0 = t * 16;
        int ra = min(r0 + lq, LTOK - 1), rb = min(r0 + lq + 8, LTOK - 1);
        uint32_t qa[2][4];
#pragma unroll
        for (int ks = 0; ks < 2; ks++) {
            float2 a0 = *(const float2*)(base + (size_t)ra * 384 + ks * 16 + 2 * lr);
            float2 a1 = *(const float2*)(base + (size_t)rb * 384 + ks * 16 + 2 * lr);
            float2 a2 = *(const float2*)(base + (size_t)ra * 384 + ks * 16 + 8 + 2 * lr);
            float2 a3 = *(const float2*)(base + (size_t)rb * 384 + ks * 16 + 8 + 2 * lr);
            qa[ks][0] = packbf(a0.x, a0.y);
            qa[ks][1] = packbf(a1.x, a1.y);
            qa[ks][2] = packbf(a2.x, a2.y);
            qa[ks][3] = packbf(a3.x, a3.y);
        }
        int labA = lab[ra], labB = lab[rb];
        const float* bra = bh + (size_t)ra * LTOK;
        const float* brb = bh + (size_t)rb * LTOK;

        float lA = 0.f, lB = 0.f;
        float o[4][4];
#pragma unroll
        for (int n = 0; n < 4; n++)
#pragma unroll
            for (int c = 0; c < 4; c++) o[n][c] = 0.f;

        for (int kb = 0; kb < 7; kb++) {
            int kb0 = kb * 56;
            float s[7][4];
#pragma unroll
            for (int nt = 0; nt < 7; nt++)
                s[nt][0] = s[nt][1] = s[nt][2] = s[nt][3] = 0.f;
#pragma unroll
            for (int ks = 0; ks < 2; ks++) {
                uint32_t bf[7][2];
#pragma unroll
                for (int p = 0; p < 3; p++)
                    LDSM4(bf[2 * p][0], bf[2 * p][1], bf[2 * p + 1][0], bf[2 * p + 1][1],
                          smuK + (unsigned)(kb0 + p * 16) * 80u + koff + ks * 32);
                LDSM2(bf[6][0], bf[6][1],
                      smuK + (unsigned)(kb0 + 48) * 80u + koff2 + ks * 32);
#pragma unroll
                for (int nt = 0; nt < 7; nt++)
                    mma_bf16(s[nt], qa[ks], bf[nt]);
            }
            // bias + mask + exp + partial sums
#pragma unroll
            for (int nt = 0; nt < 7; nt++) {
                int c0 = kb0 + nt * 8 + 2 * lr;
                float2 ba = *(const float2*)(bra + c0);
                float2 bb = *(const float2*)(brb + c0);
                if (use_mask) {
                    int l0 = lab[c0], l1 = lab[c0 + 1];
                    if (l0 != labA) ba.x -= 100.f;
                    if (l1 != labA) ba.y -= 100.f;
                    if (l0 != labB) bb.x -= 100.f;
                    if (l1 != labB) bb.y -= 100.f;
                }
                s[nt][0] = __expf(s[nt][0] + ba.x); lA += s[nt][0];
                s[nt][1] = __expf(s[nt][1] + ba.y); lA += s[nt][1];
                s[nt][2] = __expf(s[nt][2] + bb.x); lB += s[nt][2];
                s[nt][3] = __expf(s[nt][3] + bb.y); lB += s[nt][3];
            }
            // P @ V: c-frag pairs pack into k16 a-frags; V b-frags via ldmatrix
#pragma unroll
            for (int kp = 0; kp < 4; kp++) {
                uint32_t pa[4];
                pa[0] = packbf(s[2 * kp][0], s[2 * kp][1]);
                pa[1] = packbf(s[2 * kp][2], s[2 * kp][3]);
                if (kp < 3) {
                    pa[2] = packbf(s[2 * kp + 1][0], s[2 * kp + 1][1]);
                    pa[3] = packbf(s[2 * kp + 1][2], s[2 * kp + 1][3]);
                } else {
                    pa[2] = 0u; pa[3] = 0u;
                }
                uint32_t vf[4][2];
#pragma unroll
                for (int pr = 0; pr < 2; pr++)
                    LDSM4(vf[2 * pr][0], vf[2 * pr][1], vf[2 * pr + 1][0], vf[2 * pr + 1][1],
                          smuV + (unsigned)pr * 12544u + voff
                               + (unsigned)(112 * kb + 32 * kp));
#pragma unroll
                for (int ntd = 0; ntd < 4; ntd++)
                    mma_bf16(o[ntd], pa, vf[ntd]);
            }
        }
        lA += __shfl_xor_sync(0xffffffffu, lA, 1);
        lA += __shfl_xor_sync(0xffffffffu, lA, 2);
        lB += __shfl_xor_sync(0xffffffffu, lB, 1);
        lB += __shfl_xor_sync(0xffffffffu, lB, 2);
        float iA = 1.f / lA, iB = 1.f / lB;
        if (r0 + lq < LTOK) {
            uint32_t* op = (uint32_t*)out
                + ((size_t)(wnd * LTOK + r0 + lq) * CCH + head * 32) / 2;
#pragma unroll
            for (int ntd = 0; ntd < 4; ntd++)
                op[ntd * 4 + lr] = packbf(o[ntd][0] * iA, o[ntd][1] * iA);
        }
        if (r0 + lq + 8 < LTOK) {
            uint32_t* op = (uint32_t*)out
                + ((size_t)(wnd * LTOK + r0 + lq + 8) * CCH + head * 32) / 2;
#pragma unroll
            for (int ntd = 0; ntd < 4; ntd++)
                op[ntd * 4 + lr] = packbf(o[ntd][2] * iB, o[ntd][3] * iB);
        }
    }
}

// ------------------------------------------------------------------
extern "C" void kernel_launch(void* const* d_in, const int* in_sizes, int n_in,
                              void* d_out, int out_size)
{
    const float* x_in   = (const float*)d_in[0];
    const float* ln1_g  = (const float*)d_in[1];
    const float* ln1_b  = (const float*)d_in[2];
    const float* qkv_w  = (const float*)d_in[3];
    const float* qkv_b  = (const float*)d_in[4];
    const float* rpb    = (const float*)d_in[5];
    const float* proj_w = (const float*)d_in[6];
    const float* proj_b = (const float*)d_in[7];
    const float* ln2_g  = (const float*)d_in[8];
    const float* ln2_b  = (const float*)d_in[9];
    const float* fc1_w  = (const float*)d_in[10];
    const float* fc1_b  = (const float*)d_in[11];
    const float* fc2_w  = (const float*)d_in[12];
    const float* fc2_b  = (const float*)d_in[13];

    float *px, *pqkv, *pbm;
    __nv_bfloat16 *pxw, *patt, *py, *phid, *pbt;
    cudaGetSymbolAddress((void**)&px,   g_x);
    cudaGetSymbolAddress((void**)&pqkv, g_qkv);
    cudaGetSymbolAddress((void**)&pbm,  g_bm);
    cudaGetSymbolAddress((void**)&pxw,  gb_xw);
    cudaGetSymbolAddress((void**)&patt, gb_att);
    cudaGetSymbolAddress((void**)&py,   gb_y);
    cudaGetSymbolAddress((void**)&phid, gb_hid);
    cudaGetSymbolAddress((void**)&pbt,  gb_bt);

    cudaFuncSetAttribute(attn5_kernel, cudaFuncAttributeMaxDynamicSharedMemorySize, ATT5_SMEM);
    cudaFuncSetAttribute(gemm_mma_kernel, cudaFuncAttributeMaxDynamicSharedMemorySize, GEMM_SMEM);

    transpose_all_kernel<<<384, dim3(32, 8)>>>(qkv_w, proj_w, fc1_w, fc2_w, pbt);

    for (int i = 0; i < 2; i++) {
        __nv_bfloat16* bt = pbt + i * 196608;
        // LN1 reads input directly for block 0 (no copy-in)
        ln_kernel<<<NTOK / 8, 256>>>(i ? px : x_in, ln1_g + i * 128, ln1_b + i * 128,
                                     pxw, i ? 2 : 1);
        gemm_mma_kernel<<<dim3(3, 392), 256, GEMM_SMEM>>>(
            pxw, bt, qkv_b + i * 384, pqkv, nullptr, 128, 384, 0, 0);
        bias_mat_kernel<<<(LTOK * LTOK + 255) / 256, 256>>>(rpb + i * TABLE * NHEAD, pbm);
        attn5_kernel<<<dim3(NWIN, NHEAD), 256, ATT5_SMEM>>>(pqkv, pbm, patt, i);
        // proj: Cp[loc] = resid[loc] + v  (resid = x_in for block 0)
        gemm_mma_kernel<<<dim3(1, 392), 256, GEMM_SMEM>>>(
            patt, bt + 49152, proj_b + i * 128, px, i ? px : x_in, 128, 128, 1, i);
        ln_kernel<<<NTOK / 8, 256>>>(px, ln2_g + i * 128, ln2_b + i * 128, py, 0);
        gemm_mma_kernel<<<dim3(4, 392), 256, GEMM_SMEM>>>(
            py, bt + 65536, fc1_b + i * 512, phid, nullptr, 128, 512, 2, 0);
        gemm_mma_kernel<<<dim3(1, 392), 256, GEMM_SMEM>>>(
            phid, bt + 131072, fc2_b + i * 128,
            (i == 1) ? d_out : (void*)px, px, 512, 128, 3, 0);
    }
}